// round 8
// baseline (speedup 1.0000x reference)
#include <cuda_runtime.h>
#include <math.h>
#include <stdint.h>

// Problem constants
#define NB   2
#define LSEQ 1024
#define HH   8
#define DHD  64
#define DDIM 512
#define TCH  128
#define NCH  8
#define NHH  16
#define MROWS (NB*LSEQ)    // 2048
#define SROW 8320          // per-chunk state: 128x64 S + 128 den

// Device scratch (no cudaMalloc allowed)
__device__ float g_Q[MROWS*DDIM];
__device__ float g_K[MROWS*DDIM];
__device__ float g_V[MROWS*DDIM];
__device__ float g_S[NHH*NCH*SROW];
__device__ float g_SP[NHH*NCH*SROW];     // prefix (cumulative) states
__device__ float g_FQ[NHH*128*LSEQ];     // PhiQ [nh][f][t], tf32-rounded
__device__ float g_FK[NHH*128*LSEQ];     // PhiK [nh][f][t], tf32-rounded
// tf32-pre-rounded weights
__device__ float g_cWq[DDIM*DDIM];
__device__ float g_cWk[DDIM*DDIM];
__device__ float g_cWv[DDIM*DDIM];

__device__ __forceinline__ float softplus_f(float x) {
    return fmaxf(x, 0.0f) + log1pf(expf(-fabsf(x)));
}

// ---------------------------------------------------------------------------
// Primitives (compile clean for compute_103 baseline target)
// ---------------------------------------------------------------------------
__device__ __forceinline__ uint32_t smem_u32(const void* p) {
    uint32_t a;
    asm("{ .reg .u64 t; cvta.to.shared.u64 t, %1; cvt.u32.u64 %0, t; }"
        : "=r"(a) : "l"(p));
    return a;
}
#define CP_ASYNC16(dst, src) \
    asm volatile("cp.async.cg.shared.global [%0], [%1], 16;" :: "r"(dst), "l"(src))
#define CP_COMMIT()  asm volatile("cp.async.commit_group;" ::: "memory")
#define CP_WAIT(n)   asm volatile("cp.async.wait_group %0;" :: "n"(n) : "memory")

__device__ __forceinline__ void mma_tf32(float* d, const uint32_t* a, const uint32_t* b) {
    asm volatile(
        "mma.sync.aligned.m16n8k8.row.col.f32.tf32.tf32.f32 "
        "{%0,%1,%2,%3}, {%4,%5,%6,%7}, {%8,%9}, {%0,%1,%2,%3};"
        : "+f"(d[0]), "+f"(d[1]), "+f"(d[2]), "+f"(d[3])
        : "r"(a[0]), "r"(a[1]), "r"(a[2]), "r"(a[3]), "r"(b[0]), "r"(b[1]));
}
// round-to-nearest fp32 -> tf32 bits, returned as float bit-pattern
__device__ __forceinline__ float f2tf_f(float x) {
    uint32_t r;
    asm("cvt.rna.tf32.f32 %0, %1;" : "=r"(r) : "f"(x));
    return __uint_as_float(r);
}
// swizzle for proj smem: k column xor'd by row&7 (units of 4 floats)
__device__ __forceinline__ int swz(int row, int k) { return k ^ ((row & 7) << 2); }

// Padded strides (==8 mod 32 -> column-pattern fragment LDS conflict-free)
#define SFT 136
#define SVE 72
#define SQS 68   // staging stride for [t][d] tiles

// ---------------------------------------------------------------------------
// Kernel 0: round weights to tf32 (rna) once. y: 0=Wq, 1=Wk, 2=Wv
// ---------------------------------------------------------------------------
__global__ __launch_bounds__(256) void conv_tf32_kernel(
        const float* __restrict__ Wq, const float* __restrict__ Wk,
        const float* __restrict__ Wv) {
    const int y = blockIdx.y;
    const float* src = (y == 0) ? Wq : (y == 1) ? Wk : Wv;
    float* dst = (y == 0) ? g_cWq : (y == 1) ? g_cWk : g_cWv;
    int idx = blockIdx.x * 256 + threadIdx.x;
    if (idx < DDIM*DDIM/4) {
        float4 v = ((const float4*)src)[idx];
        v.x = f2tf_f(v.x); v.y = f2tf_f(v.y);
        v.z = f2tf_f(v.z); v.w = f2tf_f(v.w);
        ((float4*)dst)[idx] = v;
    }
}

// ---------------------------------------------------------------------------
// Kernel G: projection GEMM, warp tf32 mma. Block tile 128x64, 8 warps
// (warp 32x32), BK=32 double-buffered cp.async.
// ---------------------------------------------------------------------------
__global__ __launch_bounds__(256) void proj_mma_kernel(
        const float* __restrict__ query, const float* __restrict__ key) {
    extern __shared__ __align__(16) float sm[];
    float* sAbuf[2] = { sm, sm + 4096 };          // 128 x 32
    float* sBbuf[2] = { sm + 8192, sm + 10240 };  // 64 x 32

    const int which = blockIdx.z;
    const float* __restrict__ A = (which == 0) ? query : key;
    const float* __restrict__ B = (which == 0) ? g_cWq : (which == 1) ? g_cWk : g_cWv;
    float* __restrict__ out = (which == 0) ? g_Q : (which == 1) ? g_K : g_V;
    const int am0 = blockIdx.x * 128;
    const int bn0 = blockIdx.y * 64;

    const int tid = threadIdx.x;
    const int wid = tid >> 5, lane = tid & 31;
    const int gid = lane >> 2, tid4 = lane & 3;
    const int m0 = (wid & 3) * 32;
    const int n0 = (wid >> 2) * 32;

    float acc[2][4][4];
#pragma unroll
    for (int i = 0; i < 2; i++)
#pragma unroll
        for (int j = 0; j < 4; j++)
#pragma unroll
            for (int q = 0; q < 4; q++) acc[i][j][q] = 0.0f;

    auto issue_stage = [&](int kt, int buf) {
        const int k0 = kt * 32;
        uint32_t sa = smem_u32(sAbuf[buf]);
        uint32_t sb = smem_u32(sBbuf[buf]);
#pragma unroll
        for (int i = 0; i < 4; i++) {
            int f4 = tid + 256 * i;
            int row = f4 >> 3;
            int k4  = (f4 & 7) << 2;
            int soff = (row * 32 + swz(row, k4)) * 4;
            CP_ASYNC16(sa + soff, &A[(size_t)(am0 + row) * DDIM + k0 + k4]);
        }
#pragma unroll
        for (int i = 0; i < 2; i++) {
            int f4 = tid + 256 * i;
            int row = f4 >> 3;
            int k4  = (f4 & 7) << 2;
            int soff = (row * 32 + swz(row, k4)) * 4;
            CP_ASYNC16(sb + soff, &B[(size_t)(bn0 + row) * DDIM + k0 + k4]);
        }
        CP_COMMIT();
    };

    issue_stage(0, 0);

    for (int kt = 0; kt < 16; kt++) {
        const int buf = kt & 1;
        if (kt < 15) issue_stage(kt + 1, buf ^ 1);
        if (kt < 15) CP_WAIT(1); else CP_WAIT(0);
        __syncthreads();

        const uint32_t* sA32 = (const uint32_t*)sAbuf[buf];
        const uint32_t* sB32 = (const uint32_t*)sBbuf[buf];
#pragma unroll
        for (int k8 = 0; k8 < 4; k8++) {
            const int kk = k8 * 8 + tid4;
            uint32_t af[2][4];
#pragma unroll
            for (int mt = 0; mt < 2; mt++) {
                int r = m0 + mt * 16 + gid;
                af[mt][0] = sA32[r * 32 + swz(r, kk)];
                af[mt][1] = sA32[(r + 8) * 32 + swz(r + 8, kk)];
                af[mt][2] = sA32[r * 32 + swz(r, kk + 4)];
                af[mt][3] = sA32[(r + 8) * 32 + swz(r + 8, kk + 4)];
            }
            uint32_t bf[4][2];
#pragma unroll
            for (int nt = 0; nt < 4; nt++) {
                int nn = n0 + nt * 8 + gid;
                bf[nt][0] = sB32[nn * 32 + swz(nn, kk)];
                bf[nt][1] = sB32[nn * 32 + swz(nn, kk + 4)];
            }
#pragma unroll
            for (int mt = 0; mt < 2; mt++)
#pragma unroll
                for (int nt = 0; nt < 4; nt++)
                    mma_tf32(acc[mt][nt], af[mt], bf[nt]);
        }
        __syncthreads();
    }

    const bool act = (which < 2);
#pragma unroll
    for (int mt = 0; mt < 2; mt++) {
#pragma unroll
        for (int nt = 0; nt < 4; nt++) {
            int row = am0 + m0 + mt * 16 + gid;
            int col = bn0 + n0 + nt * 8 + tid4 * 2;
            float v0 = acc[mt][nt][0], v1 = acc[mt][nt][1];
            float v2 = acc[mt][nt][2], v3 = acc[mt][nt][3];
            if (act) {
                v0 = softplus_f(v0); v1 = softplus_f(v1);
                v2 = softplus_f(v2); v3 = softplus_f(v3);
            }
            *(float2*)&out[(size_t)row * DDIM + col] = make_float2(v0, v1);
            *(float2*)&out[(size_t)(row + 8) * DDIM + col] = make_float2(v2, v3);
        }
    }
}

// ---------------------------------------------------------------------------
// Kernel F: feature computation (anchored rotation recurrence) + chunk state.
// Block (nh, c), 512 threads. Writes g_FQ/g_FK [nh][f][t] (tf32-rounded),
// and for c<7 performs the chunk-state MMA into g_S.
// smem: sQs[128x68] | sKs[128x68] | sKf[128xSFT] | sV[128xSVE]
// ---------------------------------------------------------------------------
__global__ __launch_bounds__(512) void feature_kernel(
        const float* __restrict__ pw, const float* __restrict__ pb,
        const float* __restrict__ coeff) {
    extern __shared__ __align__(16) float smF[];
    float* sQs = smF;                 // [t][d] stride SQS
    float* sKs = smF + 8704;
    float* sKf = smF + 17408;         // [t][f] stride SFT
    float* sV  = smF + 17408 + 17408; // [t][e] stride SVE

    const int nh = blockIdx.x, c = blockIdx.y;
    const int n = nh >> 3, h = nh & 7;
    const int tid = threadIdx.x;
    const int wid = tid >> 5, lane = tid & 31;
    const int gid = lane >> 2, tid4 = lane & 3;

    // Stage q, k, v tiles (coalesced)
    for (int idx = tid; idx < 128*64; idx += 512) {
        int t = idx >> 6, di = idx & 63;
        int tg = c * TCH + t;
        int gbase = ((n << 10) + tg) * DDIM + (h << 6) + di;
        sQs[t*SQS + di] = g_Q[gbase];
        sKs[t*SQS + di] = g_K[gbase];
        sV[t*SVE + di]  = f2tf_f(g_V[gbase]);
    }
    __syncthreads();

    // Each thread: one d, 16 consecutive t. 3 sincosf + 15 rotation steps.
    {
        const int di = tid & 63, tpart = tid >> 6;
        const int t0 = tpart * 16;
        float w  = pw[(h << 6) + di];
        float b  = pb[(h << 6) + di];
        float cf = coeff[(h << 6) + di];
        float sk, ck, sq, cq, sw, cw;
        float a0 = (float)(c * TCH + t0) * w;
        sincosf(a0, &sk, &ck);
        sincosf(a0 + b, &sq, &cq);
        sincosf(w, &sw, &cw);
        float fqc[16], fqs[16], fkc[16], fks[16];
#pragma unroll
        for (int i = 0; i < 16; i++) {
            int t = t0 + i;
            float q = sQs[t*SQS + di] * cf;
            float k = sKs[t*SQS + di];
            float pc = f2tf_f(k * ck), ps = f2tf_f(k * sk);
            fkc[i] = pc; fks[i] = ps;
            sKf[t*SFT + di]      = pc;
            sKf[t*SFT + 64 + di] = ps;
            fqc[i] = f2tf_f(q * cq);
            fqs[i] = f2tf_f(q * sq);
            float ck2 = ck*cw - sk*sw; sk = sk*cw + ck*sw; ck = ck2;
            float cq2 = cq*cw - sq*sw; sq = sq*cw + cq*sw; cq = cq2;
        }
        size_t rbase = ((size_t)(nh * 128 + di)) * LSEQ + c * TCH + t0;
#pragma unroll
        for (int j = 0; j < 4; j++) {
            *(float4*)&g_FQ[rbase + j*4] =
                make_float4(fqc[j*4], fqc[j*4+1], fqc[j*4+2], fqc[j*4+3]);
            *(float4*)&g_FQ[rbase + (size_t)64*LSEQ + j*4] =
                make_float4(fqs[j*4], fqs[j*4+1], fqs[j*4+2], fqs[j*4+3]);
            *(float4*)&g_FK[rbase + j*4] =
                make_float4(fkc[j*4], fkc[j*4+1], fkc[j*4+2], fkc[j*4+3]);
            *(float4*)&g_FK[rbase + (size_t)64*LSEQ + j*4] =
                make_float4(fks[j*4], fks[j*4+1], fks[j*4+2], fks[j*4+3]);
        }
    }
    __syncthreads();

    if (c >= NCH-1) return;   // last chunk's state never used

    // Chunk-state MMA: S[f][e] = sum_t PhiK[t][f] * V[t][e]
    const uint32_t* sKf32 = (const uint32_t*)sKf;
    const uint32_t* sV32  = (const uint32_t*)sV;
    const int m0 = (wid & 3) * 32;
    const int n0 = (wid >> 2) * 16;
    float acc[2][2][4] = {};
#pragma unroll
    for (int k8 = 0; k8 < 16; k8++) {
        const int kk = k8 * 8 + tid4;
        uint32_t af[2][4];
#pragma unroll
        for (int mt = 0; mt < 2; mt++) {
            int r = m0 + mt * 16 + gid;
            af[mt][0] = sKf32[kk*SFT + r];
            af[mt][1] = sKf32[kk*SFT + r + 8];
            af[mt][2] = sKf32[(kk+4)*SFT + r];
            af[mt][3] = sKf32[(kk+4)*SFT + r + 8];
        }
        uint32_t bf[2][2];
#pragma unroll
        for (int nt = 0; nt < 2; nt++) {
            int nn = n0 + nt * 8 + gid;
            bf[nt][0] = sV32[kk*SVE + nn];
            bf[nt][1] = sV32[(kk+4)*SVE + nn];
        }
#pragma unroll
        for (int mt = 0; mt < 2; mt++)
#pragma unroll
            for (int nt = 0; nt < 2; nt++)
                mma_tf32(acc[mt][nt], af[mt], bf[nt]);
    }
    size_t base = (size_t)(nh * NCH + c) * SROW;
#pragma unroll
    for (int mt = 0; mt < 2; mt++) {
#pragma unroll
        for (int nt = 0; nt < 2; nt++) {
            int f = m0 + mt * 16 + gid;
            int e = n0 + nt * 8 + tid4 * 2;
            *(float2*)&g_S[base + (size_t)f * 64 + e] =
                make_float2(acc[mt][nt][0], acc[mt][nt][1]);
            *(float2*)&g_S[base + (size_t)(f + 8) * 64 + e] =
                make_float2(acc[mt][nt][2], acc[mt][nt][3]);
        }
    }
    if (tid < 128) {
        float s = 0.0f;
        for (int t = 0; t < 128; t++) s += sKf[t*SFT + tid];
        g_S[base + 8192 + tid] = s;
    }
}

// ---------------------------------------------------------------------------
// Kernel C: prefix scan of chunk states (float4, MLP=7).
// ---------------------------------------------------------------------------
__global__ __launch_bounds__(256) void scan_state_kernel() {
    const int idx = blockIdx.x * 256 + threadIdx.x;
    if (idx >= SROW/4) return;
    const float4* S4 = (const float4*)g_S;
    float4* P4 = (float4*)g_SP;
    const size_t base = (size_t)blockIdx.y * NCH * (SROW/4) + idx;
    float4 v0 = S4[base + 0*(SROW/4)];
    float4 v1 = S4[base + 1*(SROW/4)];
    float4 v2 = S4[base + 2*(SROW/4)];
    float4 v3 = S4[base + 3*(SROW/4)];
    float4 v4 = S4[base + 4*(SROW/4)];
    float4 v5 = S4[base + 5*(SROW/4)];
    float4 v6 = S4[base + 6*(SROW/4)];
    float4 r = v0;
    P4[base + 1*(SROW/4)] = r;
    r.x += v1.x; r.y += v1.y; r.z += v1.z; r.w += v1.w;
    P4[base + 2*(SROW/4)] = r;
    r.x += v2.x; r.y += v2.y; r.z += v2.z; r.w += v2.w;
    P4[base + 3*(SROW/4)] = r;
    r.x += v3.x; r.y += v3.y; r.z += v3.z; r.w += v3.w;
    P4[base + 4*(SROW/4)] = r;
    r.x += v4.x; r.y += v4.y; r.z += v4.z; r.w += v4.w;
    P4[base + 5*(SROW/4)] = r;
    r.x += v5.x; r.y += v5.y; r.z += v5.z; r.w += v5.w;
    P4[base + 6*(SROW/4)] = r;
    r.x += v6.x; r.y += v6.y; r.z += v6.z; r.w += v6.w;
    P4[base + 7*(SROW/4)] = r;
}

// ---------------------------------------------------------------------------
// Kernel D: per-chunk output. Phase 1a = pure coalesced loads of PhiQ/PhiK.
// ---------------------------------------------------------------------------
__global__ __launch_bounds__(512, 1) void attn_out_kernel(float* __restrict__ out) {
    extern __shared__ __align__(16) float smD[];
    float* sQT   = smD;
    float* sKT   = smD + 17408;
    float* sV    = smD + 34816;
    float* sP    = smD + 44032;
    float* sPden = smD + 53248;
    float* sDen  = smD + 53376;

    const int nh = blockIdx.x, c = blockIdx.y;
    const int n = nh >> 3, h = nh & 7;
    const int tid = threadIdx.x;
    const int wid = tid >> 5, lane = tid & 31;
    const int gid = lane >> 2, tid4 = lane & 3;

    if (tid < 128) sDen[tid] = 0.0f;

    // Phase 1a: load PhiQ/PhiK tiles (float4 coalesced) + V
    for (int j = tid; j < 128*32; j += 512) {
        int f = j >> 5, q4 = (j & 31) << 2;
        size_t gb = ((size_t)(nh * 128 + f)) * LSEQ + c * TCH + q4;
        *(float4*)&sQT[f*SFT + q4] = *(const float4*)&g_FQ[gb];
        *(float4*)&sKT[f*SFT + q4] = *(const float4*)&g_FK[gb];
    }
    for (int idx = tid; idx < 128*64; idx += 512) {
        int t = idx >> 6, di = idx & 63;
        int tg = c * TCH + t;
        sV[t*SVE + di] = f2tf_f(g_V[((n << 10) + tg) * DDIM + (h << 6) + di]);
    }
    // Phase 1b: prefix state (single coalesced read of cumulative state)
    if (c > 0) {
        size_t base = ((size_t)nh * NCH + c) * SROW;
        for (int idx = tid; idx < 128*64; idx += 512) {
            int f = idx >> 6, e = idx & 63;
            sP[f*SVE + e] = f2tf_f(g_SP[base + idx]);
        }
        if (tid < 128) sPden[tid] = g_SP[base + 8192 + tid];
    }
    __syncthreads();

    const uint32_t* sQT32 = (const uint32_t*)sQT;
    const uint32_t* sKT32 = (const uint32_t*)sKT;
    const uint32_t* sV32  = (const uint32_t*)sV;
    const uint32_t* sP32  = (const uint32_t*)sP;

    // Phase 2: scores (128x128, k = feature 128)
    const int m2 = (wid & 3) * 32;
    const int n2 = (wid >> 2) * 32;
    float acc[2][4][4] = {};
#pragma unroll
    for (int k8 = 0; k8 < 16; k8++) {
        const int kk = k8 * 8 + tid4;
        uint32_t af[2][4];
#pragma unroll
        for (int mt = 0; mt < 2; mt++) {
            int r = m2 + mt * 16 + gid;
            af[mt][0] = sQT32[kk*SFT + r];
            af[mt][1] = sQT32[kk*SFT + r + 8];
            af[mt][2] = sQT32[(kk+4)*SFT + r];
            af[mt][3] = sQT32[(kk+4)*SFT + r + 8];
        }
        uint32_t bf[4][2];
#pragma unroll
        for (int nt = 0; nt < 4; nt++) {
            int nn = n2 + nt * 8 + gid;
            bf[nt][0] = sKT32[kk*SFT + nn];
            bf[nt][1] = sKT32[(kk+4)*SFT + nn];
        }
#pragma unroll
        for (int mt = 0; mt < 2; mt++)
#pragma unroll
            for (int nt = 0; nt < 4; nt++)
                mma_tf32(acc[mt][nt], af[mt], bf[nt]);
    }
    __syncthreads();   // all warps done reading sKT

    // Causal mask -> write transposed sAT[col][row] (round at store), row sums
    float* sAT = sKT;
#pragma unroll
    for (int mt = 0; mt < 2; mt++) {
        int r = m2 + mt * 16 + gid;
        float rs_lo = 0.0f, rs_hi = 0.0f;
#pragma unroll
        for (int nt = 0; nt < 4; nt++) {
            int cb = n2 + nt * 8 + tid4 * 2;
            float v0 = (cb     <= r)     ? acc[mt][nt][0] : 0.0f;
            float v1 = (cb + 1 <= r)     ? acc[mt][nt][1] : 0.0f;
            float v2 = (cb     <= r + 8) ? acc[mt][nt][2] : 0.0f;
            float v3 = (cb + 1 <= r + 8) ? acc[mt][nt][3] : 0.0f;
            sAT[cb * SFT + r]           = f2tf_f(v0);
            sAT[(cb + 1) * SFT + r]     = f2tf_f(v1);
            sAT[cb * SFT + r + 8]       = f2tf_f(v2);
            sAT[(cb + 1) * SFT + r + 8] = f2tf_f(v3);
            rs_lo += v0 + v1;
            rs_hi += v2 + v3;
        }
        atomicAdd(&sDen[r], rs_lo);
        atomicAdd(&sDen[r + 8], rs_hi);
    }
    __syncthreads();

    const uint32_t* sAT32 = (const uint32_t*)sAT;

    // Phase 3: out = A@V + PhiQ^T@P  (128x64), warp tile 32x16
    const int m3 = (wid & 3) * 32;
    const int n3 = (wid >> 2) * 16;
    float o[2][2][4] = {};
#pragma unroll
    for (int k8 = 0; k8 < 16; k8++) {
        const int kk = k8 * 8 + tid4;
        uint32_t af[2][4];
#pragma unroll
        for (int mt = 0; mt < 2; mt++) {
            int r = m3 + mt * 16 + gid;
            af[mt][0] = sAT32[kk*SFT + r];
            af[mt][1] = sAT32[kk*SFT + r + 8];
            af[mt][2] = sAT32[(kk+4)*SFT + r];
            af[mt][3] = sAT32[(kk+4)*SFT + r + 8];
        }
        uint32_t bf[2][2];
#pragma unroll
        for (int nt = 0; nt < 2; nt++) {
            int nn = n3 + nt * 8 + gid;
            bf[nt][0] = sV32[kk*SVE + nn];
            bf[nt][1] = sV32[(kk+4)*SVE + nn];
        }
#pragma unroll
        for (int mt = 0; mt < 2; mt++)
#pragma unroll
            for (int nt = 0; nt < 2; nt++)
                mma_tf32(o[mt][nt], af[mt], bf[nt]);
    }
    if (c > 0) {
#pragma unroll
        for (int k8 = 0; k8 < 16; k8++) {
            const int kk = k8 * 8 + tid4;
            uint32_t af[2][4];
#pragma unroll
            for (int mt = 0; mt < 2; mt++) {
                int r = m3 + mt * 16 + gid;
                af[mt][0] = sQT32[kk*SFT + r];
                af[mt][1] = sQT32[kk*SFT + r + 8];
                af[mt][2] = sQT32[(kk+4)*SFT + r];
                af[mt][3] = sQT32[(kk+4)*SFT + r + 8];
            }
            uint32_t bf[2][2];
#pragma unroll
            for (int nt = 0; nt < 2; nt++) {
                int nn = n3 + nt * 8 + gid;
                bf[nt][0] = sP32[kk*SVE + nn];
                bf[nt][1] = sP32[(kk+4)*SVE + nn];
            }
#pragma unroll
            for (int mt = 0; mt < 2; mt++)
#pragma unroll
                for (int nt = 0; nt < 2; nt++)
                    mma_tf32(o[mt][nt], af[mt], bf[nt]);
        }
        int t = tid & 127, part = tid >> 7;
        float s = 0.0f;
        for (int f = part * 32; f < part * 32 + 32; f++)
            s += sQT[f*SFT + t] * sPden[f];
        atomicAdd(&sDen[t], s);
    }
    __syncthreads();

    // Phase 4: normalize + write (N, Lq, H*dh)
#pragma unroll
    for (int mt = 0; mt < 2; mt++) {
        int r = m3 + mt * 16 + gid;
        float inv_lo = 1.0f / sDen[r];
        float inv_hi = 1.0f / sDen[r + 8];
        int tg_lo = c * TCH + r;
        int tg_hi = tg_lo + 8;
#pragma unroll
        for (int nt = 0; nt < 2; nt++) {
            int e = n3 + nt * 8 + tid4 * 2;
            *(float2*)&out[((n << 10) + tg_lo) * DDIM + (h << 6) + e] =
                make_float2(o[mt][nt][0] * inv_lo, o[mt][nt][1] * inv_lo);
            *(float2*)&out[((n << 10) + tg_hi) * DDIM + (h << 6) + e] =
                make_float2(o[mt][nt][2] * inv_hi, o[mt][nt][3] * inv_hi);
        }
    }
}

// ---------------------------------------------------------------------------
extern "C" void kernel_launch(void* const* d_in, const int* in_sizes, int n_in,
                              void* d_out, int out_size) {
    const float* query = (const float*)d_in[0];
    const float* key   = (const float*)d_in[1];
    const float* Wq    = (const float*)d_in[2];
    const float* Wk    = (const float*)d_in[3];
    const float* Wv    = (const float*)d_in[4];
    const float* coeff = (const float*)d_in[5];
    const float* pw    = (const float*)d_in[6];
    const float* pb    = (const float*)d_in[7];
    float* out = (float*)d_out;

    cudaFuncSetAttribute(proj_mma_kernel,
                         cudaFuncAttributeMaxDynamicSharedMemorySize, 49152);
    cudaFuncSetAttribute(feature_kernel,
                         cudaFuncAttributeMaxDynamicSharedMemorySize, 176128);
    cudaFuncSetAttribute(attn_out_kernel,
                         cudaFuncAttributeMaxDynamicSharedMemorySize, 214528);

    conv_tf32_kernel<<<dim3(DDIM*DDIM/4/256, 3), 256>>>(Wq, Wk, Wv);
    proj_mma_kernel<<<dim3(MROWS/128, DDIM/64, 3), 256, 49152>>>(query, key);
    feature_kernel<<<dim3(NHH, NCH), 512, 176128>>>(pw, pb, coeff);
    scan_state_kernel<<<dim3((SROW/4 + 255)/256, NHH), 256>>>();
    attn_out_kernel<<<dim3(NHH, NCH), 512, 214528>>>(out);
}

// round 9
// speedup vs baseline: 1.0777x; 1.0777x over previous
#include <cuda_runtime.h>
#include <math.h>
#include <stdint.h>

// Problem constants
#define NB   2
#define LSEQ 1024
#define HH   8
#define DHD  64
#define DDIM 512
#define TCH  128
#define NCH  8
#define NHH  16
#define MROWS (NB*LSEQ)    // 2048
#define SROW 8320          // per-chunk state: 128x64 S + 128 den

// Device scratch (no cudaMalloc allowed)
__device__ float g_Q[MROWS*DDIM];
__device__ float g_K[MROWS*DDIM];
__device__ float g_V[MROWS*DDIM];
__device__ float g_S[NHH*NCH*SROW];
__device__ float g_SP[NHH*NCH*SROW];   // prefix (cumulative) states
// tf32-pre-rounded weights
__device__ float g_cWq[DDIM*DDIM];
__device__ float g_cWk[DDIM*DDIM];
__device__ float g_cWv[DDIM*DDIM];

__device__ __forceinline__ float softplus_f(float x) {
    return fmaxf(x, 0.0f) + log1pf(expf(-fabsf(x)));
}

// ---------------------------------------------------------------------------
// Primitives (compile clean for compute_103 baseline target)
// ---------------------------------------------------------------------------
__device__ __forceinline__ uint32_t smem_u32(const void* p) {
    uint32_t a;
    asm("{ .reg .u64 t; cvta.to.shared.u64 t, %1; cvt.u32.u64 %0, t; }"
        : "=r"(a) : "l"(p));
    return a;
}
#define CP_ASYNC16(dst, src) \
    asm volatile("cp.async.cg.shared.global [%0], [%1], 16;" :: "r"(dst), "l"(src))
#define CP_COMMIT()  asm volatile("cp.async.commit_group;" ::: "memory")
#define CP_WAIT(n)   asm volatile("cp.async.wait_group %0;" :: "n"(n) : "memory")

__device__ __forceinline__ void mma_tf32(float* d, const uint32_t* a, const uint32_t* b) {
    asm volatile(
        "mma.sync.aligned.m16n8k8.row.col.f32.tf32.tf32.f32 "
        "{%0,%1,%2,%3}, {%4,%5,%6,%7}, {%8,%9}, {%0,%1,%2,%3};"
        : "+f"(d[0]), "+f"(d[1]), "+f"(d[2]), "+f"(d[3])
        : "r"(a[0]), "r"(a[1]), "r"(a[2]), "r"(a[3]), "r"(b[0]), "r"(b[1]));
}
// round-to-nearest fp32 -> tf32 bits, returned as float bit-pattern
__device__ __forceinline__ float f2tf_f(float x) {
    uint32_t r;
    asm("cvt.rna.tf32.f32 %0, %1;" : "=r"(r) : "f"(x));
    return __uint_as_float(r);
}
// swizzle for proj smem: k column xor'd by row&7 (units of 4 floats)
__device__ __forceinline__ int swz(int row, int k) { return k ^ ((row & 7) << 2); }

// Padded strides (==8 mod 32 -> column-pattern fragment LDS conflict-free)
#define SFT 136
#define SVE 72

// ---------------------------------------------------------------------------
// Kernel 0: round weights to tf32 (rna) once. y: 0=Wq, 1=Wk, 2=Wv
// ---------------------------------------------------------------------------
__global__ __launch_bounds__(256) void conv_tf32_kernel(
        const float* __restrict__ Wq, const float* __restrict__ Wk,
        const float* __restrict__ Wv) {
    const int y = blockIdx.y;
    const float* src = (y == 0) ? Wq : (y == 1) ? Wk : Wv;
    float* dst = (y == 0) ? g_cWq : (y == 1) ? g_cWk : g_cWv;
    int idx = blockIdx.x * 256 + threadIdx.x;
    if (idx < DDIM*DDIM/4) {
        float4 v = ((const float4*)src)[idx];
        v.x = f2tf_f(v.x); v.y = f2tf_f(v.y);
        v.z = f2tf_f(v.z); v.w = f2tf_f(v.w);
        ((float4*)dst)[idx] = v;
    }
}

// ---------------------------------------------------------------------------
// Kernel G: projection GEMM, warp tf32 mma. Block tile 128x64, 8 warps
// (warp 32x32), BK=32 double-buffered cp.async. 2 blocks/SM target.
// ---------------------------------------------------------------------------
__global__ __launch_bounds__(256, 2) void proj_mma_kernel(
        const float* __restrict__ query, const float* __restrict__ key) {
    extern __shared__ __align__(16) float sm[];
    float* sAbuf[2] = { sm, sm + 4096 };          // 128 x 32
    float* sBbuf[2] = { sm + 8192, sm + 10240 };  // 64 x 32

    const int which = blockIdx.z;
    const float* __restrict__ A = (which == 0) ? query : key;
    const float* __restrict__ B = (which == 0) ? g_cWq : (which == 1) ? g_cWk : g_cWv;
    float* __restrict__ out = (which == 0) ? g_Q : (which == 1) ? g_K : g_V;
    const int am0 = blockIdx.x * 128;
    const int bn0 = blockIdx.y * 64;

    const int tid = threadIdx.x;
    const int wid = tid >> 5, lane = tid & 31;
    const int gid = lane >> 2, tid4 = lane & 3;
    const int m0 = (wid & 3) * 32;
    const int n0 = (wid >> 2) * 32;

    float acc[2][4][4];
#pragma unroll
    for (int i = 0; i < 2; i++)
#pragma unroll
        for (int j = 0; j < 4; j++)
#pragma unroll
            for (int q = 0; q < 4; q++) acc[i][j][q] = 0.0f;

    auto issue_stage = [&](int kt, int buf) {
        const int k0 = kt * 32;
        uint32_t sa = smem_u32(sAbuf[buf]);
        uint32_t sb = smem_u32(sBbuf[buf]);
#pragma unroll
        for (int i = 0; i < 4; i++) {
            int f4 = tid + 256 * i;
            int row = f4 >> 3;
            int k4  = (f4 & 7) << 2;
            int soff = (row * 32 + swz(row, k4)) * 4;
            CP_ASYNC16(sa + soff, &A[(size_t)(am0 + row) * DDIM + k0 + k4]);
        }
#pragma unroll
        for (int i = 0; i < 2; i++) {
            int f4 = tid + 256 * i;
            int row = f4 >> 3;
            int k4  = (f4 & 7) << 2;
            int soff = (row * 32 + swz(row, k4)) * 4;
            CP_ASYNC16(sb + soff, &B[(size_t)(bn0 + row) * DDIM + k0 + k4]);
        }
        CP_COMMIT();
    };

    issue_stage(0, 0);

    for (int kt = 0; kt < 16; kt++) {
        const int buf = kt & 1;
        if (kt < 15) issue_stage(kt + 1, buf ^ 1);
        if (kt < 15) CP_WAIT(1); else CP_WAIT(0);
        __syncthreads();

        const uint32_t* sA32 = (const uint32_t*)sAbuf[buf];
        const uint32_t* sB32 = (const uint32_t*)sBbuf[buf];
#pragma unroll
        for (int k8 = 0; k8 < 4; k8++) {
            const int kk = k8 * 8 + tid4;
            uint32_t af[2][4];
#pragma unroll
            for (int mt = 0; mt < 2; mt++) {
                int r = m0 + mt * 16 + gid;
                af[mt][0] = sA32[r * 32 + swz(r, kk)];
                af[mt][1] = sA32[(r + 8) * 32 + swz(r + 8, kk)];
                af[mt][2] = sA32[r * 32 + swz(r, kk + 4)];
                af[mt][3] = sA32[(r + 8) * 32 + swz(r + 8, kk + 4)];
            }
            uint32_t bf[4][2];
#pragma unroll
            for (int nt = 0; nt < 4; nt++) {
                int nn = n0 + nt * 8 + gid;
                bf[nt][0] = sB32[nn * 32 + swz(nn, kk)];
                bf[nt][1] = sB32[nn * 32 + swz(nn, kk + 4)];
            }
#pragma unroll
            for (int mt = 0; mt < 2; mt++)
#pragma unroll
                for (int nt = 0; nt < 4; nt++)
                    mma_tf32(acc[mt][nt], af[mt], bf[nt]);
        }
        __syncthreads();
    }

    const bool act = (which < 2);
#pragma unroll
    for (int mt = 0; mt < 2; mt++) {
#pragma unroll
        for (int nt = 0; nt < 4; nt++) {
            int row = am0 + m0 + mt * 16 + gid;
            int col = bn0 + n0 + nt * 8 + tid4 * 2;
            float v0 = acc[mt][nt][0], v1 = acc[mt][nt][1];
            float v2 = acc[mt][nt][2], v3 = acc[mt][nt][3];
            if (act) {
                v0 = softplus_f(v0); v1 = softplus_f(v1);
                v2 = softplus_f(v2); v3 = softplus_f(v3);
            }
            *(float2*)&out[(size_t)row * DDIM + col] = make_float2(v0, v1);
            *(float2*)&out[(size_t)(row + 8) * DDIM + col] = make_float2(v2, v3);
        }
    }
}

// ---------------------------------------------------------------------------
// Kernel B: per-chunk KV state via warp mma. 1024 threads, 32 warps,
// warp tile 16x16. Chunks 0..6 only (7 unused).
// ---------------------------------------------------------------------------
__global__ __launch_bounds__(1024) void chunk_state_kernel(const float* __restrict__ pw) {
    extern __shared__ __align__(16) float smB[];
    float* sKf = smB;                // [t][f] stride SFT
    float* sV  = smB + 128*SFT;      // [t][e] stride SVE

    const int nh = blockIdx.x, c = blockIdx.y;
    const int n = nh >> 3, h = nh & 7;
    const int tid = threadIdx.x;
    const int wid = tid >> 5, lane = tid & 31;
    const int gid = lane >> 2, tid4 = lane & 3;

    for (int idx = tid; idx < 128*64; idx += 1024) {
        int t = idx >> 6, di = idx & 63;
        int tg = c * TCH + t;
        int gbase = ((n << 10) + tg) * DDIM + (h << 6) + di;
        float kv = g_K[gbase];
        float vv = g_V[gbase];
        float w  = pw[(h << 6) + di];
        float s, cs;
        sincosf((float)tg * w, &s, &cs);
        sKf[t*SFT + di]      = f2tf_f(kv * cs);
        sKf[t*SFT + 64 + di] = f2tf_f(kv * s);
        sV[t*SVE + di]       = f2tf_f(vv);
    }
    __syncthreads();

    const uint32_t* sKf32 = (const uint32_t*)sKf;
    const uint32_t* sV32  = (const uint32_t*)sV;
    const int m0 = (wid & 7) * 16;   // f tile (8 x 16 = 128)
    const int n0 = (wid >> 3) * 16;  // e tile (4 x 16 = 64)
    float acc[2][4] = {};
#pragma unroll
    for (int k8 = 0; k8 < 16; k8++) {
        const int kk = k8 * 8 + tid4;
        uint32_t af[4];
        {
            int r = m0 + gid;
            af[0] = sKf32[kk*SFT + r];
            af[1] = sKf32[kk*SFT + r + 8];
            af[2] = sKf32[(kk+4)*SFT + r];
            af[3] = sKf32[(kk+4)*SFT + r + 8];
        }
        uint32_t bf[2][2];
#pragma unroll
        for (int nt = 0; nt < 2; nt++) {
            int nn = n0 + nt * 8 + gid;
            bf[nt][0] = sV32[kk*SVE + nn];
            bf[nt][1] = sV32[(kk+4)*SVE + nn];
        }
#pragma unroll
        for (int nt = 0; nt < 2; nt++)
            mma_tf32(acc[nt], af, bf[nt]);
    }
    size_t base = (size_t)(nh * NCH + c) * SROW;
#pragma unroll
    for (int nt = 0; nt < 2; nt++) {
        int f = m0 + gid;
        int e = n0 + nt * 8 + tid4 * 2;
        *(float2*)&g_S[base + (size_t)f * 64 + e] =
            make_float2(acc[nt][0], acc[nt][1]);
        *(float2*)&g_S[base + (size_t)(f + 8) * 64 + e] =
            make_float2(acc[nt][2], acc[nt][3]);
    }
    if (tid < 512) {
        // den column: 4 partials per f, combined via smem-free shuffle-less split
        int f = tid & 127, part = tid >> 7;   // 4 parts of 32 t
        float s = 0.0f;
        for (int t = part * 32; t < part * 32 + 32; t++) s += sKf[t*SFT + f];
        // combine: part 0 writes after atomic-free tree via shared atomics
        atomicAdd(&g_S[base + 8192 + f], (part == 0) ? s : s);
    }
}

// ---------------------------------------------------------------------------
// Kernel C: prefix scan of chunk states (float4, MLP=7).
// ---------------------------------------------------------------------------
__global__ __launch_bounds__(256) void scan_state_kernel() {
    const int idx = blockIdx.x * 256 + threadIdx.x;
    if (idx >= SROW/4) return;
    const float4* S4 = (const float4*)g_S;
    float4* P4 = (float4*)g_SP;
    const size_t base = (size_t)blockIdx.y * NCH * (SROW/4) + idx;
    float4 v0 = S4[base + 0*(SROW/4)];
    float4 v1 = S4[base + 1*(SROW/4)];
    float4 v2 = S4[base + 2*(SROW/4)];
    float4 v3 = S4[base + 3*(SROW/4)];
    float4 v4 = S4[base + 4*(SROW/4)];
    float4 v5 = S4[base + 5*(SROW/4)];
    float4 v6 = S4[base + 6*(SROW/4)];
    float4 r = v0;
    P4[base + 1*(SROW/4)] = r;
    r.x += v1.x; r.y += v1.y; r.z += v1.z; r.w += v1.w;
    P4[base + 2*(SROW/4)] = r;
    r.x += v2.x; r.y += v2.y; r.z += v2.z; r.w += v2.w;
    P4[base + 3*(SROW/4)] = r;
    r.x += v3.x; r.y += v3.y; r.z += v3.z; r.w += v3.w;
    P4[base + 4*(SROW/4)] = r;
    r.x += v4.x; r.y += v4.y; r.z += v4.z; r.w += v4.w;
    P4[base + 5*(SROW/4)] = r;
    r.x += v5.x; r.y += v5.y; r.z += v5.z; r.w += v5.w;
    P4[base + 6*(SROW/4)] = r;
    r.x += v6.x; r.y += v6.y; r.z += v6.z; r.w += v6.w;
    P4[base + 7*(SROW/4)] = r;
}

// ---------------------------------------------------------------------------
// Kernel Z: zero the den column of g_S (chunk_state now accumulates it
// atomically across 4 partials).
// ---------------------------------------------------------------------------
__global__ __launch_bounds__(128) void zero_den_kernel() {
    size_t base = (size_t)blockIdx.x * SROW + 8192;   // blockIdx.x over nh*NCH
    g_S[base + threadIdx.x] = 0.0f;
}

// ---------------------------------------------------------------------------
// Kernel D: per-chunk output. 1024 threads (32 warps) for latency hiding.
// ---------------------------------------------------------------------------
__global__ __launch_bounds__(1024, 1) void attn_out_kernel(
        const float* __restrict__ pw, const float* __restrict__ pb,
        const float* __restrict__ coeff, float* __restrict__ out) {
    extern __shared__ __align__(16) float smD[];
    float* sQT   = smD;
    float* sKT   = smD + 17408;
    float* sV    = smD + 34816;
    float* sP    = smD + 44032;
    float* sPden = smD + 53248;
    float* sDen  = smD + 53376;
    float* sCB   = smD + 53504;
    float* sSB   = smD + 53568;

    const int nh = blockIdx.x, c = blockIdx.y;
    const int n = nh >> 3, h = nh & 7;
    const int tid = threadIdx.x;
    const int wid = tid >> 5, lane = tid & 31;
    const int gid = lane >> 2, tid4 = lane & 3;

    if (tid < 128) sDen[tid] = 0.0f;
    if (tid >= 128 && tid < 192) {
        int di = tid - 128;
        float sb_, cb_;
        sincosf(pb[(h << 6) + di], &sb_, &cb_);
        sCB[di] = cb_; sSB[di] = sb_;
    }
    __syncthreads();

    // Phase 1a: features + V (one accurate sincos per element + rotation)
    for (int idx = tid; idx < 128*64; idx += 1024) {
        int t = idx >> 6, di = idx & 63;
        int tg = c * TCH + t;
        int gbase = ((n << 10) + tg) * DDIM + (h << 6) + di;
        float qv = g_Q[gbase], kv = g_K[gbase], vv = g_V[gbase];
        float w  = pw[(h << 6) + di];
        float cf = coeff[(h << 6) + di];
        float sk, ck;
        sincosf((float)tg * w, &sk, &ck);
        float cb_ = sCB[di], sb_ = sSB[di];
        float cq = ck * cb_ - sk * sb_;
        float sq = sk * cb_ + ck * sb_;
        float qc = qv * cf;
        sQT[di*SFT + t]        = f2tf_f(qc * cq);
        sQT[(64 + di)*SFT + t] = f2tf_f(qc * sq);
        sKT[di*SFT + t]        = f2tf_f(kv * ck);
        sKT[(64 + di)*SFT + t] = f2tf_f(kv * sk);
        sV[t*SVE + di]         = f2tf_f(vv);
    }
    // Phase 1b: prefix state (single coalesced read of cumulative state)
    if (c > 0) {
        size_t base = ((size_t)nh * NCH + c) * SROW;
        for (int idx = tid; idx < 128*64; idx += 1024) {
            int f = idx >> 6, e = idx & 63;
            sP[f*SVE + e] = f2tf_f(g_SP[base + idx]);
        }
        if (tid < 128) sPden[tid] = g_SP[base + 8192 + tid];
    }
    __syncthreads();

    const uint32_t* sQT32 = (const uint32_t*)sQT;
    const uint32_t* sKT32 = (const uint32_t*)sKT;
    const uint32_t* sV32  = (const uint32_t*)sV;
    const uint32_t* sP32  = (const uint32_t*)sP;

    // Phase 2: scores (128x128, k = feature 128), 32 warps, warp tile 32x16
    const int m2 = (wid & 3) * 32;
    const int n2 = (wid >> 2) * 16;
    float acc[2][2][4] = {};
#pragma unroll
    for (int k8 = 0; k8 < 16; k8++) {
        const int kk = k8 * 8 + tid4;
        uint32_t af[2][4];
#pragma unroll
        for (int mt = 0; mt < 2; mt++) {
            int r = m2 + mt * 16 + gid;
            af[mt][0] = sQT32[kk*SFT + r];
            af[mt][1] = sQT32[kk*SFT + r + 8];
            af[mt][2] = sQT32[(kk+4)*SFT + r];
            af[mt][3] = sQT32[(kk+4)*SFT + r + 8];
        }
        uint32_t bf[2][2];
#pragma unroll
        for (int nt = 0; nt < 2; nt++) {
            int nn = n2 + nt * 8 + gid;
            bf[nt][0] = sKT32[kk*SFT + nn];
            bf[nt][1] = sKT32[(kk+4)*SFT + nn];
        }
#pragma unroll
        for (int mt = 0; mt < 2; mt++)
#pragma unroll
            for (int nt = 0; nt < 2; nt++)
                mma_tf32(acc[mt][nt], af[mt], bf[nt]);
    }
    __syncthreads();   // all warps done reading sKT

    // Causal mask -> write transposed sAT[col][row] (round at store), row sums
    float* sAT = sKT;
#pragma unroll
    for (int mt = 0; mt < 2; mt++) {
        int r = m2 + mt * 16 + gid;
        float rs_lo = 0.0f, rs_hi = 0.0f;
#pragma unroll
        for (int nt = 0; nt < 2; nt++) {
            int cb = n2 + nt * 8 + tid4 * 2;
            float v0 = (cb     <= r)     ? acc[mt][nt][0] : 0.0f;
            float v1 = (cb + 1 <= r)     ? acc[mt][nt][1] : 0.0f;
            float v2 = (cb     <= r + 8) ? acc[mt][nt][2] : 0.0f;
            float v3 = (cb + 1 <= r + 8) ? acc[mt][nt][3] : 0.0f;
            sAT[cb * SFT + r]           = f2tf_f(v0);
            sAT[(cb + 1) * SFT + r]     = f2tf_f(v1);
            sAT[cb * SFT + r + 8]       = f2tf_f(v2);
            sAT[(cb + 1) * SFT + r + 8] = f2tf_f(v3);
            rs_lo += v0 + v1;
            rs_hi += v2 + v3;
        }
        atomicAdd(&sDen[r], rs_lo);
        atomicAdd(&sDen[r + 8], rs_hi);
    }
    __syncthreads();

    const uint32_t* sAT32 = (const uint32_t*)sAT;

    // Phase 3: out = A@V + PhiQ^T@P  (128x64), 32 warps, warp tile 16x16
    const int m3 = (wid & 7) * 16;
    const int n3 = (wid >> 3) * 16;
    float o[2][4] = {};
#pragma unroll
    for (int k8 = 0; k8 < 16; k8++) {
        const int kk = k8 * 8 + tid4;
        uint32_t af[4];
        {
            int r = m3 + gid;
            af[0] = sAT32[kk*SFT + r];
            af[1] = sAT32[kk*SFT + r + 8];
            af[2] = sAT32[(kk+4)*SFT + r];
            af[3] = sAT32[(kk+4)*SFT + r + 8];
        }
        uint32_t bf[2][2];
#pragma unroll
        for (int nt = 0; nt < 2; nt++) {
            int nn = n3 + nt * 8 + gid;
            bf[nt][0] = sV32[kk*SVE + nn];
            bf[nt][1] = sV32[(kk+4)*SVE + nn];
        }
#pragma unroll
        for (int nt = 0; nt < 2; nt++)
            mma_tf32(o[nt], af, bf[nt]);
    }
    if (c > 0) {
#pragma unroll
        for (int k8 = 0; k8 < 16; k8++) {
            const int kk = k8 * 8 + tid4;
            uint32_t af[4];
            {
                int r = m3 + gid;
                af[0] = sQT32[kk*SFT + r];
                af[1] = sQT32[kk*SFT + r + 8];
                af[2] = sQT32[(kk+4)*SFT + r];
                af[3] = sQT32[(kk+4)*SFT + r + 8];
            }
            uint32_t bf[2][2];
#pragma unroll
            for (int nt = 0; nt < 2; nt++) {
                int nn = n3 + nt * 8 + gid;
                bf[nt][0] = sP32[kk*SVE + nn];
                bf[nt][1] = sP32[(kk+4)*SVE + nn];
            }
#pragma unroll
            for (int nt = 0; nt < 2; nt++)
                mma_tf32(o[nt], af, bf[nt]);
        }
        // den inter-chunk term (fp32, 8-way split over f)
        int t = tid & 127, part = tid >> 7;
        float s = 0.0f;
        for (int f = part * 16; f < part * 16 + 16; f++)
            s += sQT[f*SFT + t] * sPden[f];
        atomicAdd(&sDen[t], s);
    }
    __syncthreads();

    // Phase 4: normalize + write (N, Lq, H*dh)
    {
        int r = m3 + gid;
        float inv_lo = 1.0f / sDen[r];
        float inv_hi = 1.0f / sDen[r + 8];
        int tg_lo = c * TCH + r;
        int tg_hi = tg_lo + 8;
#pragma unroll
        for (int nt = 0; nt < 2; nt++) {
            int e = n3 + nt * 8 + tid4 * 2;
            *(float2*)&out[((n << 10) + tg_lo) * DDIM + (h << 6) + e] =
                make_float2(o[nt][0] * inv_lo, o[nt][1] * inv_lo);
            *(float2*)&out[((n << 10) + tg_hi) * DDIM + (h << 6) + e] =
                make_float2(o[nt][2] * inv_hi, o[nt][3] * inv_hi);
        }
    }
}

// ---------------------------------------------------------------------------
extern "C" void kernel_launch(void* const* d_in, const int* in_sizes, int n_in,
                              void* d_out, int out_size) {
    const float* query = (const float*)d_in[0];
    const float* key   = (const float*)d_in[1];
    const float* Wq    = (const float*)d_in[2];
    const float* Wk    = (const float*)d_in[3];
    const float* Wv    = (const float*)d_in[4];
    const float* coeff = (const float*)d_in[5];
    const float* pw    = (const float*)d_in[6];
    const float* pb    = (const float*)d_in[7];
    float* out = (float*)d_out;

    cudaFuncSetAttribute(proj_mma_kernel,
                         cudaFuncAttributeMaxDynamicSharedMemorySize, 49152);
    cudaFuncSetAttribute(chunk_state_kernel,
                         cudaFuncAttributeMaxDynamicSharedMemorySize, 107520);
    cudaFuncSetAttribute(attn_out_kernel,
                         cudaFuncAttributeMaxDynamicSharedMemorySize, 214528);

    conv_tf32_kernel<<<dim3(DDIM*DDIM/4/256, 3), 256>>>(Wq, Wk, Wv);
    proj_mma_kernel<<<dim3(MROWS/128, DDIM/64, 3), 256, 49152>>>(query, key);
    zero_den_kernel<<<NHH*NCH, 128>>>();
    chunk_state_kernel<<<dim3(NHH, NCH-1), 1024, 107520>>>(pw);
    scan_state_kernel<<<dim3((SROW/4 + 255)/256, NHH), 256>>>();
    attn_out_kernel<<<dim3(NHH, NCH), 1024, 214528>>>(pw, pb, coeff, out);
}

// round 10
// speedup vs baseline: 1.1034x; 1.0238x over previous
#include <cuda_runtime.h>
#include <math.h>
#include <stdint.h>

// Problem constants
#define NB   2
#define LSEQ 1024
#define HH   8
#define DHD  64
#define DDIM 512
#define TCH  128
#define NCH  8
#define NHH  16
#define MROWS (NB*LSEQ)    // 2048
#define SROW 8320          // per-chunk state: 128x64 S + 128 den

// Device scratch (no cudaMalloc allowed)
__device__ float g_Q[MROWS*DDIM];
__device__ float g_K[MROWS*DDIM];
__device__ float g_V[MROWS*DDIM];
__device__ float g_S[NHH*NCH*SROW];
// tf32-pre-rounded weights
__device__ float g_cWq[DDIM*DDIM];
__device__ float g_cWk[DDIM*DDIM];
__device__ float g_cWv[DDIM*DDIM];

__device__ __forceinline__ float softplus_f(float x) {
    return fmaxf(x, 0.0f) + log1pf(expf(-fabsf(x)));
}

// ---------------------------------------------------------------------------
// Primitives (compile clean for compute_103 baseline target)
// ---------------------------------------------------------------------------
__device__ __forceinline__ uint32_t smem_u32(const void* p) {
    uint32_t a;
    asm("{ .reg .u64 t; cvta.to.shared.u64 t, %1; cvt.u32.u64 %0, t; }"
        : "=r"(a) : "l"(p));
    return a;
}
#define CP_ASYNC16(dst, src) \
    asm volatile("cp.async.cg.shared.global [%0], [%1], 16;" :: "r"(dst), "l"(src))
#define CP_COMMIT()  asm volatile("cp.async.commit_group;" ::: "memory")
#define CP_WAIT(n)   asm volatile("cp.async.wait_group %0;" :: "n"(n) : "memory")

__device__ __forceinline__ void mma_tf32(float* d, const uint32_t* a, const uint32_t* b) {
    asm volatile(
        "mma.sync.aligned.m16n8k8.row.col.f32.tf32.tf32.f32 "
        "{%0,%1,%2,%3}, {%4,%5,%6,%7}, {%8,%9}, {%0,%1,%2,%3};"
        : "+f"(d[0]), "+f"(d[1]), "+f"(d[2]), "+f"(d[3])
        : "r"(a[0]), "r"(a[1]), "r"(a[2]), "r"(a[3]), "r"(b[0]), "r"(b[1]));
}
// round-to-nearest fp32 -> tf32 bits, returned as float bit-pattern
__device__ __forceinline__ float f2tf_f(float x) {
    uint32_t r;
    asm("cvt.rna.tf32.f32 %0, %1;" : "=r"(r) : "f"(x));
    return __uint_as_float(r);
}
// swizzle for proj smem: k column xor'd by row&7 (units of 4 floats)
__device__ __forceinline__ int swz(int row, int k) { return k ^ ((row & 7) << 2); }

// Padded strides (==8 mod 32 -> column-pattern fragment LDS conflict-free)
#define SFT 136
#define SVE 72

// ---------------------------------------------------------------------------
// Kernel 0: round weights to tf32 (rna) once. y: 0=Wq, 1=Wk, 2=Wv
// ---------------------------------------------------------------------------
__global__ __launch_bounds__(256) void conv_tf32_kernel(
        const float* __restrict__ Wq, const float* __restrict__ Wk,
        const float* __restrict__ Wv) {
    const int y = blockIdx.y;
    const float* src = (y == 0) ? Wq : (y == 1) ? Wk : Wv;
    float* dst = (y == 0) ? g_cWq : (y == 1) ? g_cWk : g_cWv;
    int idx = blockIdx.x * 256 + threadIdx.x;
    if (idx < DDIM*DDIM/4) {
        float4 v = ((const float4*)src)[idx];
        v.x = f2tf_f(v.x); v.y = f2tf_f(v.y);
        v.z = f2tf_f(v.z); v.w = f2tf_f(v.w);
        ((float4*)dst)[idx] = v;
    }
}

// ---------------------------------------------------------------------------
// Kernel G: projection GEMM, warp tf32 mma. Block tile 128x64, 8 warps
// (warp 32x32), BK=32 double-buffered cp.async. 2 blocks/SM target.
// ---------------------------------------------------------------------------
__global__ __launch_bounds__(256, 2) void proj_mma_kernel(
        const float* __restrict__ query, const float* __restrict__ key) {
    extern __shared__ __align__(16) float sm[];
    float* sAbuf[2] = { sm, sm + 4096 };          // 128 x 32
    float* sBbuf[2] = { sm + 8192, sm + 10240 };  // 64 x 32

    const int which = blockIdx.z;
    const float* __restrict__ A = (which == 0) ? query : key;
    const float* __restrict__ B = (which == 0) ? g_cWq : (which == 1) ? g_cWk : g_cWv;
    float* __restrict__ out = (which == 0) ? g_Q : (which == 1) ? g_K : g_V;
    const int am0 = blockIdx.x * 128;
    const int bn0 = blockIdx.y * 64;

    const int tid = threadIdx.x;
    const int wid = tid >> 5, lane = tid & 31;
    const int gid = lane >> 2, tid4 = lane & 3;
    const int m0 = (wid & 3) * 32;
    const int n0 = (wid >> 2) * 32;

    float acc[2][4][4];
#pragma unroll
    for (int i = 0; i < 2; i++)
#pragma unroll
        for (int j = 0; j < 4; j++)
#pragma unroll
            for (int q = 0; q < 4; q++) acc[i][j][q] = 0.0f;

    auto issue_stage = [&](int kt, int buf) {
        const int k0 = kt * 32;
        uint32_t sa = smem_u32(sAbuf[buf]);
        uint32_t sb = smem_u32(sBbuf[buf]);
#pragma unroll
        for (int i = 0; i < 4; i++) {
            int f4 = tid + 256 * i;
            int row = f4 >> 3;
            int k4  = (f4 & 7) << 2;
            int soff = (row * 32 + swz(row, k4)) * 4;
            CP_ASYNC16(sa + soff, &A[(size_t)(am0 + row) * DDIM + k0 + k4]);
        }
#pragma unroll
        for (int i = 0; i < 2; i++) {
            int f4 = tid + 256 * i;
            int row = f4 >> 3;
            int k4  = (f4 & 7) << 2;
            int soff = (row * 32 + swz(row, k4)) * 4;
            CP_ASYNC16(sb + soff, &B[(size_t)(bn0 + row) * DDIM + k0 + k4]);
        }
        CP_COMMIT();
    };

    issue_stage(0, 0);

    for (int kt = 0; kt < 16; kt++) {
        const int buf = kt & 1;
        if (kt < 15) issue_stage(kt + 1, buf ^ 1);
        if (kt < 15) CP_WAIT(1); else CP_WAIT(0);
        __syncthreads();

        const uint32_t* sA32 = (const uint32_t*)sAbuf[buf];
        const uint32_t* sB32 = (const uint32_t*)sBbuf[buf];
#pragma unroll
        for (int k8 = 0; k8 < 4; k8++) {
            const int kk = k8 * 8 + tid4;
            uint32_t af[2][4];
#pragma unroll
            for (int mt = 0; mt < 2; mt++) {
                int r = m0 + mt * 16 + gid;
                af[mt][0] = sA32[r * 32 + swz(r, kk)];
                af[mt][1] = sA32[(r + 8) * 32 + swz(r + 8, kk)];
                af[mt][2] = sA32[r * 32 + swz(r, kk + 4)];
                af[mt][3] = sA32[(r + 8) * 32 + swz(r + 8, kk + 4)];
            }
            uint32_t bf[4][2];
#pragma unroll
            for (int nt = 0; nt < 4; nt++) {
                int nn = n0 + nt * 8 + gid;
                bf[nt][0] = sB32[nn * 32 + swz(nn, kk)];
                bf[nt][1] = sB32[nn * 32 + swz(nn, kk + 4)];
            }
#pragma unroll
            for (int mt = 0; mt < 2; mt++)
#pragma unroll
                for (int nt = 0; nt < 4; nt++)
                    mma_tf32(acc[mt][nt], af[mt], bf[nt]);
        }
        __syncthreads();
    }

    const bool act = (which < 2);
#pragma unroll
    for (int mt = 0; mt < 2; mt++) {
#pragma unroll
        for (int nt = 0; nt < 4; nt++) {
            int row = am0 + m0 + mt * 16 + gid;
            int col = bn0 + n0 + nt * 8 + tid4 * 2;
            float v0 = acc[mt][nt][0], v1 = acc[mt][nt][1];
            float v2 = acc[mt][nt][2], v3 = acc[mt][nt][3];
            if (act) {
                v0 = softplus_f(v0); v1 = softplus_f(v1);
                v2 = softplus_f(v2); v3 = softplus_f(v3);
            }
            *(float2*)&out[(size_t)row * DDIM + col] = make_float2(v0, v1);
            *(float2*)&out[(size_t)(row + 8) * DDIM + col] = make_float2(v2, v3);
        }
    }
}

// ---------------------------------------------------------------------------
// Kernel B: per-chunk KV state via warp mma. 512 threads, 16 warps,
// warp tile 32x16. No atomics; den via per-f serial smem reduction.
// Chunks 0..6 only (7 unused).
// ---------------------------------------------------------------------------
__global__ __launch_bounds__(512) void chunk_state_kernel(const float* __restrict__ pw) {
    extern __shared__ __align__(16) float smB[];
    float* sKf = smB;                // [t][f] stride SFT
    float* sV  = smB + 128*SFT;      // [t][e] stride SVE

    const int nh = blockIdx.x, c = blockIdx.y;
    const int n = nh >> 3, h = nh & 7;
    const int tid = threadIdx.x;
    const int wid = tid >> 5, lane = tid & 31;
    const int gid = lane >> 2, tid4 = lane & 3;

    for (int idx = tid; idx < 128*64; idx += 512) {
        int t = idx >> 6, di = idx & 63;
        int tg = c * TCH + t;
        int gbase = ((n << 10) + tg) * DDIM + (h << 6) + di;
        float kv = g_K[gbase];
        float vv = g_V[gbase];
        float w  = pw[(h << 6) + di];
        float s, cs;
        sincosf((float)tg * w, &s, &cs);
        sKf[t*SFT + di]      = f2tf_f(kv * cs);
        sKf[t*SFT + 64 + di] = f2tf_f(kv * s);
        sV[t*SVE + di]       = f2tf_f(vv);
    }
    __syncthreads();

    const uint32_t* sKf32 = (const uint32_t*)sKf;
    const uint32_t* sV32  = (const uint32_t*)sV;
    const int m0 = (wid & 3) * 32;
    const int n0 = (wid >> 2) * 16;
    float acc[2][2][4] = {};
#pragma unroll
    for (int k8 = 0; k8 < 16; k8++) {
        const int kk = k8 * 8 + tid4;
        uint32_t af[2][4];
#pragma unroll
        for (int mt = 0; mt < 2; mt++) {
            int r = m0 + mt * 16 + gid;
            af[mt][0] = sKf32[kk*SFT + r];
            af[mt][1] = sKf32[kk*SFT + r + 8];
            af[mt][2] = sKf32[(kk+4)*SFT + r];
            af[mt][3] = sKf32[(kk+4)*SFT + r + 8];
        }
        uint32_t bf[2][2];
#pragma unroll
        for (int nt = 0; nt < 2; nt++) {
            int nn = n0 + nt * 8 + gid;
            bf[nt][0] = sV32[kk*SVE + nn];
            bf[nt][1] = sV32[(kk+4)*SVE + nn];
        }
#pragma unroll
        for (int mt = 0; mt < 2; mt++)
#pragma unroll
            for (int nt = 0; nt < 2; nt++)
                mma_tf32(acc[mt][nt], af[mt], bf[nt]);
    }
    size_t base = (size_t)(nh * NCH + c) * SROW;
#pragma unroll
    for (int mt = 0; mt < 2; mt++) {
#pragma unroll
        for (int nt = 0; nt < 2; nt++) {
            int f = m0 + mt * 16 + gid;
            int e = n0 + nt * 8 + tid4 * 2;
            *(float2*)&g_S[base + (size_t)f * 64 + e] =
                make_float2(acc[mt][nt][0], acc[mt][nt][1]);
            *(float2*)&g_S[base + (size_t)(f + 8) * 64 + e] =
                make_float2(acc[mt][nt][2], acc[mt][nt][3]);
        }
    }
    if (tid < 128) {
        float s = 0.0f;
        for (int t = 0; t < 128; t++) s += sKf[t*SFT + tid];
        g_S[base + 8192 + tid] = s;
    }
}

// ---------------------------------------------------------------------------
// Kernel D: per-chunk output. 1024 threads. Inline MLP-7 prefix reduction
// (no scan kernel); V staged via cp.async overlapping feature math.
// ---------------------------------------------------------------------------
__global__ __launch_bounds__(1024, 1) void attn_out_kernel(
        const float* __restrict__ pw, const float* __restrict__ pb,
        const float* __restrict__ coeff, float* __restrict__ out) {
    extern __shared__ __align__(16) float smD[];
    float* sQT   = smD;
    float* sKT   = smD + 17408;
    float* sV    = smD + 34816;
    float* sP    = smD + 44032;
    float* sPden = smD + 53248;
    float* sDen  = smD + 53376;
    float* sCB   = smD + 53504;
    float* sSB   = smD + 53568;

    const int nh = blockIdx.x, c = blockIdx.y;
    const int n = nh >> 3, h = nh & 7;
    const int tid = threadIdx.x;
    const int wid = tid >> 5, lane = tid & 31;
    const int gid = lane >> 2, tid4 = lane & 3;

    // V via cp.async (overlaps with feature compute below). Truncation to
    // tf32 happens in the MMA (raw bits); acceptable numerator-only bias.
    {
        uint32_t sv = smem_u32(sV);
#pragma unroll
        for (int j = 0; j < 2; j++) {
            int idx = (tid + j * 1024) * 4;   // 4 floats per cp
            int t = idx >> 6, di = idx & 63;
            CP_ASYNC16(sv + (t*SVE + di)*4,
                       &g_V[((n << 10) + c * TCH + t) * DDIM + (h << 6) + di]);
        }
        CP_COMMIT();
    }

    if (tid < 128) sDen[tid] = 0.0f;
    if (tid >= 128 && tid < 192) {
        int di = tid - 128;
        float sb_, cb_;
        sincosf(pb[(h << 6) + di], &sb_, &cb_);
        sCB[di] = cb_; sSB[di] = sb_;
    }
    __syncthreads();

    // Phase 1a: features (one accurate sincos per element + bias rotation)
    for (int idx = tid; idx < 128*64; idx += 1024) {
        int t = idx >> 6, di = idx & 63;
        int tg = c * TCH + t;
        int gbase = ((n << 10) + tg) * DDIM + (h << 6) + di;
        float qv = g_Q[gbase], kv = g_K[gbase];
        float w  = pw[(h << 6) + di];
        float cf = coeff[(h << 6) + di];
        float sk, ck;
        sincosf((float)tg * w, &sk, &ck);
        float cb_ = sCB[di], sb_ = sSB[di];
        float cq = ck * cb_ - sk * sb_;
        float sq = sk * cb_ + ck * sb_;
        float qc = qv * cf;
        sQT[di*SFT + t]        = f2tf_f(qc * cq);
        sQT[(64 + di)*SFT + t] = f2tf_f(qc * sq);
        sKT[di*SFT + t]        = f2tf_f(kv * ck);
        sKT[(64 + di)*SFT + t] = f2tf_f(kv * sk);
    }
    // Phase 1b: inline prefix reduction over chunk states (MLP=7 batched,
    // unconditional loads, predicated adds).
    if (c > 0) {
        size_t sb = (size_t)nh * NCH * SROW;
        for (int idx = tid; idx < SROW; idx += 1024) {
            float v0 = g_S[sb + 0*SROW + idx];
            float v1 = g_S[sb + 1*SROW + idx];
            float v2 = g_S[sb + 2*SROW + idx];
            float v3 = g_S[sb + 3*SROW + idx];
            float v4 = g_S[sb + 4*SROW + idx];
            float v5 = g_S[sb + 5*SROW + idx];
            float v6 = g_S[sb + 6*SROW + idx];
            float a = v0;
            if (c > 1) a += v1;
            if (c > 2) a += v2;
            if (c > 3) a += v3;
            if (c > 4) a += v4;
            if (c > 5) a += v5;
            if (c > 6) a += v6;
            if (idx < 8192) sP[(idx >> 6)*SVE + (idx & 63)] = f2tf_f(a);
            else            sPden[idx - 8192] = a;
        }
    }
    CP_WAIT(0);
    __syncthreads();

    const uint32_t* sQT32 = (const uint32_t*)sQT;
    const uint32_t* sKT32 = (const uint32_t*)sKT;
    const uint32_t* sV32  = (const uint32_t*)sV;
    const uint32_t* sP32  = (const uint32_t*)sP;

    // Phase 2: scores (128x128, k = feature 128), 32 warps, warp tile 32x16
    const int m2 = (wid & 3) * 32;
    const int n2 = (wid >> 2) * 16;
    float acc[2][2][4] = {};
#pragma unroll
    for (int k8 = 0; k8 < 16; k8++) {
        const int kk = k8 * 8 + tid4;
        uint32_t af[2][4];
#pragma unroll
        for (int mt = 0; mt < 2; mt++) {
            int r = m2 + mt * 16 + gid;
            af[mt][0] = sQT32[kk*SFT + r];
            af[mt][1] = sQT32[kk*SFT + r + 8];
            af[mt][2] = sQT32[(kk+4)*SFT + r];
            af[mt][3] = sQT32[(kk+4)*SFT + r + 8];
        }
        uint32_t bf[2][2];
#pragma unroll
        for (int nt = 0; nt < 2; nt++) {
            int nn = n2 + nt * 8 + gid;
            bf[nt][0] = sKT32[kk*SFT + nn];
            bf[nt][1] = sKT32[(kk+4)*SFT + nn];
        }
#pragma unroll
        for (int mt = 0; mt < 2; mt++)
#pragma unroll
            for (int nt = 0; nt < 2; nt++)
                mma_tf32(acc[mt][nt], af[mt], bf[nt]);
    }
    __syncthreads();   // all warps done reading sKT

    // Causal mask -> write transposed sAT[col][row] (round at store), row sums
    float* sAT = sKT;
#pragma unroll
    for (int mt = 0; mt < 2; mt++) {
        int r = m2 + mt * 16 + gid;
        float rs_lo = 0.0f, rs_hi = 0.0f;
#pragma unroll
        for (int nt = 0; nt < 2; nt++) {
            int cb = n2 + nt * 8 + tid4 * 2;
            float v0 = (cb     <= r)     ? acc[mt][nt][0] : 0.0f;
            float v1 = (cb + 1 <= r)     ? acc[mt][nt][1] : 0.0f;
            float v2 = (cb     <= r + 8) ? acc[mt][nt][2] : 0.0f;
            float v3 = (cb + 1 <= r + 8) ? acc[mt][nt][3] : 0.0f;
            sAT[cb * SFT + r]           = f2tf_f(v0);
            sAT[(cb + 1) * SFT + r]     = f2tf_f(v1);
            sAT[cb * SFT + r + 8]       = f2tf_f(v2);
            sAT[(cb + 1) * SFT + r + 8] = f2tf_f(v3);
            rs_lo += v0 + v1;
            rs_hi += v2 + v3;
        }
        atomicAdd(&sDen[r], rs_lo);
        atomicAdd(&sDen[r + 8], rs_hi);
    }
    __syncthreads();

    const uint32_t* sAT32 = (const uint32_t*)sAT;

    // Phase 3: out = A@V + PhiQ^T@P  (128x64), 32 warps, warp tile 16x16
    const int m3 = (wid & 7) * 16;
    const int n3 = (wid >> 3) * 16;
    float o[2][4] = {};
#pragma unroll
    for (int k8 = 0; k8 < 16; k8++) {
        const int kk = k8 * 8 + tid4;
        uint32_t af[4];
        {
            int r = m3 + gid;
            af[0] = sAT32[kk*SFT + r];
            af[1] = sAT32[kk*SFT + r + 8];
            af[2] = sAT32[(kk+4)*SFT + r];
            af[3] = sAT32[(kk+4)*SFT + r + 8];
        }
        uint32_t bf[2][2];
#pragma unroll
        for (int nt = 0; nt < 2; nt++) {
            int nn = n3 + nt * 8 + gid;
            bf[nt][0] = sV32[kk*SVE + nn];
            bf[nt][1] = sV32[(kk+4)*SVE + nn];
        }
#pragma unroll
        for (int nt = 0; nt < 2; nt++)
            mma_tf32(o[nt], af, bf[nt]);
    }
    if (c > 0) {
#pragma unroll
        for (int k8 = 0; k8 < 16; k8++) {
            const int kk = k8 * 8 + tid4;
            uint32_t af[4];
            {
                int r = m3 + gid;
                af[0] = sQT32[kk*SFT + r];
                af[1] = sQT32[kk*SFT + r + 8];
                af[2] = sQT32[(kk+4)*SFT + r];
                af[3] = sQT32[(kk+4)*SFT + r + 8];
            }
            uint32_t bf[2][2];
#pragma unroll
            for (int nt = 0; nt < 2; nt++) {
                int nn = n3 + nt * 8 + gid;
                bf[nt][0] = sP32[kk*SVE + nn];
                bf[nt][1] = sP32[(kk+4)*SVE + nn];
            }
#pragma unroll
            for (int nt = 0; nt < 2; nt++)
                mma_tf32(o[nt], af, bf[nt]);
        }
        // den inter-chunk term (fp32, 8-way split over f)
        int t = tid & 127, part = tid >> 7;
        float s = 0.0f;
        for (int f = part * 16; f < part * 16 + 16; f++)
            s += sQT[f*SFT + t] * sPden[f];
        atomicAdd(&sDen[t], s);
    }
    __syncthreads();

    // Phase 4: normalize + write (N, Lq, H*dh)
    {
        int r = m3 + gid;
        float inv_lo = 1.0f / sDen[r];
        float inv_hi = 1.0f / sDen[r + 8];
        int tg_lo = c * TCH + r;
        int tg_hi = tg_lo + 8;
#pragma unroll
        for (int nt = 0; nt < 2; nt++) {
            int e = n3 + nt * 8 + tid4 * 2;
            *(float2*)&out[((n << 10) + tg_lo) * DDIM + (h << 6) + e] =
                make_float2(o[nt][0] * inv_lo, o[nt][1] * inv_lo);
            *(float2*)&out[((n << 10) + tg_hi) * DDIM + (h << 6) + e] =
                make_float2(o[nt][2] * inv_hi, o[nt][3] * inv_hi);
        }
    }
}

// ---------------------------------------------------------------------------
extern "C" void kernel_launch(void* const* d_in, const int* in_sizes, int n_in,
                              void* d_out, int out_size) {
    const float* query = (const float*)d_in[0];
    const float* key   = (const float*)d_in[1];
    const float* Wq    = (const float*)d_in[2];
    const float* Wk    = (const float*)d_in[3];
    const float* Wv    = (const float*)d_in[4];
    const float* coeff = (const float*)d_in[5];
    const float* pw    = (const float*)d_in[6];
    const float* pb    = (const float*)d_in[7];
    float* out = (float*)d_out;

    cudaFuncSetAttribute(proj_mma_kernel,
                         cudaFuncAttributeMaxDynamicSharedMemorySize, 49152);
    cudaFuncSetAttribute(chunk_state_kernel,
                         cudaFuncAttributeMaxDynamicSharedMemorySize, 107520);
    cudaFuncSetAttribute(attn_out_kernel,
                         cudaFuncAttributeMaxDynamicSharedMemorySize, 214528);

    conv_tf32_kernel<<<dim3(DDIM*DDIM/4/256, 3), 256>>>(Wq, Wk, Wv);
    proj_mma_kernel<<<dim3(MROWS/128, DDIM/64, 3), 256, 49152>>>(query, key);
    chunk_state_kernel<<<dim3(NHH, NCH-1), 512, 107520>>>(pw);
    attn_out_kernel<<<dim3(NHH, NCH), 1024, 214528>>>(pw, pb, coeff, out);
}

// round 11
// speedup vs baseline: 1.1052x; 1.0016x over previous
#include <cuda_runtime.h>
#include <math.h>
#include <stdint.h>

// Problem constants
#define NB   2
#define LSEQ 1024
#define HH   8
#define DHD  64
#define DDIM 512
#define TCH  128
#define NCH  8
#define NHH  16
#define MROWS (NB*LSEQ)    // 2048
#define SROW 8320          // per-chunk state: 128x64 S + 128 den

// Device scratch (no cudaMalloc allowed)
__device__ float g_Q[MROWS*DDIM];
__device__ float g_K[MROWS*DDIM];
__device__ float g_V[MROWS*DDIM];
__device__ float g_S[NHH*NCH*SROW];
// tf32-pre-rounded weights
__device__ float g_cWq[DDIM*DDIM];
__device__ float g_cWk[DDIM*DDIM];
__device__ float g_cWv[DDIM*DDIM];

__device__ __forceinline__ float softplus_f(float x) {
    return fmaxf(x, 0.0f) + log1pf(expf(-fabsf(x)));
}

// ---------------------------------------------------------------------------
// Primitives (compile clean for compute_103 baseline target)
// ---------------------------------------------------------------------------
__device__ __forceinline__ uint32_t smem_u32(const void* p) {
    uint32_t a;
    asm("{ .reg .u64 t; cvta.to.shared.u64 t, %1; cvt.u32.u64 %0, t; }"
        : "=r"(a) : "l"(p));
    return a;
}
#define CP_ASYNC16(dst, src) \
    asm volatile("cp.async.cg.shared.global [%0], [%1], 16;" :: "r"(dst), "l"(src))
#define CP_COMMIT()  asm volatile("cp.async.commit_group;" ::: "memory")
#define CP_WAIT(n)   asm volatile("cp.async.wait_group %0;" :: "n"(n) : "memory")

__device__ __forceinline__ void mma_tf32(float* d, const uint32_t* a, const uint32_t* b) {
    asm volatile(
        "mma.sync.aligned.m16n8k8.row.col.f32.tf32.tf32.f32 "
        "{%0,%1,%2,%3}, {%4,%5,%6,%7}, {%8,%9}, {%0,%1,%2,%3};"
        : "+f"(d[0]), "+f"(d[1]), "+f"(d[2]), "+f"(d[3])
        : "r"(a[0]), "r"(a[1]), "r"(a[2]), "r"(a[3]), "r"(b[0]), "r"(b[1]));
}
// round-to-nearest fp32 -> tf32 bits, returned as float bit-pattern
__device__ __forceinline__ float f2tf_f(float x) {
    uint32_t r;
    asm("cvt.rna.tf32.f32 %0, %1;" : "=r"(r) : "f"(x));
    return __uint_as_float(r);
}
// swizzle for proj smem: k column xor'd by row&7 (units of 4 floats)
__device__ __forceinline__ int swz(int row, int k) { return k ^ ((row & 7) << 2); }

// Padded strides (==8 mod 32 -> column-pattern fragment LDS conflict-free)
#define SFT 136
#define SVE 72

// ---------------------------------------------------------------------------
// Kernel 0: round weights to tf32 (rna) once. y: 0=Wq, 1=Wk, 2=Wv
// ---------------------------------------------------------------------------
__global__ __launch_bounds__(256) void conv_tf32_kernel(
        const float* __restrict__ Wq, const float* __restrict__ Wk,
        const float* __restrict__ Wv) {
    const int y = blockIdx.y;
    const float* src = (y == 0) ? Wq : (y == 1) ? Wk : Wv;
    float* dst = (y == 0) ? g_cWq : (y == 1) ? g_cWk : g_cWv;
    int idx = blockIdx.x * 256 + threadIdx.x;
    if (idx < DDIM*DDIM/4) {
        float4 v = ((const float4*)src)[idx];
        v.x = f2tf_f(v.x); v.y = f2tf_f(v.y);
        v.z = f2tf_f(v.z); v.w = f2tf_f(v.w);
        ((float4*)dst)[idx] = v;
    }
}

// ---------------------------------------------------------------------------
// Kernel G: projection GEMM, warp tf32 mma. Block tile 128x64, 4 warps
// (warp 64x32), BK=32 double-buffered cp.async. 4 blocks/SM => single wave.
// ---------------------------------------------------------------------------
__global__ __launch_bounds__(128, 4) void proj_mma_kernel(
        const float* __restrict__ query, const float* __restrict__ key) {
    extern __shared__ __align__(16) float sm[];
    float* sAbuf[2] = { sm, sm + 4096 };          // 128 x 32
    float* sBbuf[2] = { sm + 8192, sm + 10240 };  // 64 x 32

    const int which = blockIdx.z;
    const float* __restrict__ A = (which == 0) ? query : key;
    const float* __restrict__ B = (which == 0) ? g_cWq : (which == 1) ? g_cWk : g_cWv;
    float* __restrict__ out = (which == 0) ? g_Q : (which == 1) ? g_K : g_V;
    const int am0 = blockIdx.x * 128;
    const int bn0 = blockIdx.y * 64;

    const int tid = threadIdx.x;
    const int wid = tid >> 5, lane = tid & 31;
    const int gid = lane >> 2, tid4 = lane & 3;
    const int m0 = (wid & 1) * 64;   // 2 m-tiles of 64
    const int n0 = (wid >> 1) * 32;  // 2 n-tiles of 32

    float acc[4][4][4];
#pragma unroll
    for (int i = 0; i < 4; i++)
#pragma unroll
        for (int j = 0; j < 4; j++)
#pragma unroll
            for (int q = 0; q < 4; q++) acc[i][j][q] = 0.0f;

    auto issue_stage = [&](int kt, int buf) {
        const int k0 = kt * 32;
        uint32_t sa = smem_u32(sAbuf[buf]);
        uint32_t sb = smem_u32(sBbuf[buf]);
#pragma unroll
        for (int i = 0; i < 8; i++) {
            int f4 = tid + 128 * i;
            int row = f4 >> 3;
            int k4  = (f4 & 7) << 2;
            int soff = (row * 32 + swz(row, k4)) * 4;
            CP_ASYNC16(sa + soff, &A[(size_t)(am0 + row) * DDIM + k0 + k4]);
        }
#pragma unroll
        for (int i = 0; i < 4; i++) {
            int f4 = tid + 128 * i;
            int row = f4 >> 3;
            int k4  = (f4 & 7) << 2;
            int soff = (row * 32 + swz(row, k4)) * 4;
            CP_ASYNC16(sb + soff, &B[(size_t)(bn0 + row) * DDIM + k0 + k4]);
        }
        CP_COMMIT();
    };

    issue_stage(0, 0);

    for (int kt = 0; kt < 16; kt++) {
        const int buf = kt & 1;
        if (kt < 15) issue_stage(kt + 1, buf ^ 1);
        if (kt < 15) CP_WAIT(1); else CP_WAIT(0);
        __syncthreads();

        const uint32_t* sA32 = (const uint32_t*)sAbuf[buf];
        const uint32_t* sB32 = (const uint32_t*)sBbuf[buf];
#pragma unroll
        for (int k8 = 0; k8 < 4; k8++) {
            const int kk = k8 * 8 + tid4;
            uint32_t af[4][4];
#pragma unroll
            for (int mt = 0; mt < 4; mt++) {
                int r = m0 + mt * 16 + gid;
                af[mt][0] = sA32[r * 32 + swz(r, kk)];
                af[mt][1] = sA32[(r + 8) * 32 + swz(r + 8, kk)];
                af[mt][2] = sA32[r * 32 + swz(r, kk + 4)];
                af[mt][3] = sA32[(r + 8) * 32 + swz(r + 8, kk + 4)];
            }
            uint32_t bf[4][2];
#pragma unroll
            for (int nt = 0; nt < 4; nt++) {
                int nn = n0 + nt * 8 + gid;
                bf[nt][0] = sB32[nn * 32 + swz(nn, kk)];
                bf[nt][1] = sB32[nn * 32 + swz(nn, kk + 4)];
            }
#pragma unroll
            for (int mt = 0; mt < 4; mt++)
#pragma unroll
                for (int nt = 0; nt < 4; nt++)
                    mma_tf32(acc[mt][nt], af[mt], bf[nt]);
        }
        __syncthreads();
    }

    const bool act = (which < 2);
#pragma unroll
    for (int mt = 0; mt < 4; mt++) {
#pragma unroll
        for (int nt = 0; nt < 4; nt++) {
            int row = am0 + m0 + mt * 16 + gid;
            int col = bn0 + n0 + nt * 8 + tid4 * 2;
            float v0 = acc[mt][nt][0], v1 = acc[mt][nt][1];
            float v2 = acc[mt][nt][2], v3 = acc[mt][nt][3];
            if (act) {
                v0 = softplus_f(v0); v1 = softplus_f(v1);
                v2 = softplus_f(v2); v3 = softplus_f(v3);
            }
            *(float2*)&out[(size_t)row * DDIM + col] = make_float2(v0, v1);
            *(float2*)&out[(size_t)(row + 8) * DDIM + col] = make_float2(v2, v3);
        }
    }
}

// ---------------------------------------------------------------------------
// Kernel B: per-chunk KV state via warp mma. 512 threads, 16 warps,
// warp tile 32x16. No atomics. Chunks 0..6 only (7 unused).
// ---------------------------------------------------------------------------
__global__ __launch_bounds__(512) void chunk_state_kernel(const float* __restrict__ pw) {
    extern __shared__ __align__(16) float smB[];
    float* sKf = smB;                // [t][f] stride SFT
    float* sV  = smB + 128*SFT;      // [t][e] stride SVE

    const int nh = blockIdx.x, c = blockIdx.y;
    const int n = nh >> 3, h = nh & 7;
    const int tid = threadIdx.x;
    const int wid = tid >> 5, lane = tid & 31;
    const int gid = lane >> 2, tid4 = lane & 3;

    for (int idx = tid; idx < 128*64; idx += 512) {
        int t = idx >> 6, di = idx & 63;
        int tg = c * TCH + t;
        int gbase = ((n << 10) + tg) * DDIM + (h << 6) + di;
        float kv = g_K[gbase];
        float vv = g_V[gbase];
        float w  = pw[(h << 6) + di];
        float s, cs;
        sincosf((float)tg * w, &s, &cs);
        sKf[t*SFT + di]      = f2tf_f(kv * cs);
        sKf[t*SFT + 64 + di] = f2tf_f(kv * s);
        sV[t*SVE + di]       = f2tf_f(vv);
    }
    __syncthreads();

    const uint32_t* sKf32 = (const uint32_t*)sKf;
    const uint32_t* sV32  = (const uint32_t*)sV;
    const int m0 = (wid & 3) * 32;
    const int n0 = (wid >> 2) * 16;
    float acc[2][2][4] = {};
#pragma unroll
    for (int k8 = 0; k8 < 16; k8++) {
        const int kk = k8 * 8 + tid4;
        uint32_t af[2][4];
#pragma unroll
        for (int mt = 0; mt < 2; mt++) {
            int r = m0 + mt * 16 + gid;
            af[mt][0] = sKf32[kk*SFT + r];
            af[mt][1] = sKf32[kk*SFT + r + 8];
            af[mt][2] = sKf32[(kk+4)*SFT + r];
            af[mt][3] = sKf32[(kk+4)*SFT + r + 8];
        }
        uint32_t bf[2][2];
#pragma unroll
        for (int nt = 0; nt < 2; nt++) {
            int nn = n0 + nt * 8 + gid;
            bf[nt][0] = sV32[kk*SVE + nn];
            bf[nt][1] = sV32[(kk+4)*SVE + nn];
        }
#pragma unroll
        for (int mt = 0; mt < 2; mt++)
#pragma unroll
            for (int nt = 0; nt < 2; nt++)
                mma_tf32(acc[mt][nt], af[mt], bf[nt]);
    }
    size_t base = (size_t)(nh * NCH + c) * SROW;
#pragma unroll
    for (int mt = 0; mt < 2; mt++) {
#pragma unroll
        for (int nt = 0; nt < 2; nt++) {
            int f = m0 + mt * 16 + gid;
            int e = n0 + nt * 8 + tid4 * 2;
            *(float2*)&g_S[base + (size_t)f * 64 + e] =
                make_float2(acc[mt][nt][0], acc[mt][nt][1]);
            *(float2*)&g_S[base + (size_t)(f + 8) * 64 + e] =
                make_float2(acc[mt][nt][2], acc[mt][nt][3]);
        }
    }
    if (tid < 128) {
        float s = 0.0f;
        for (int t = 0; t < 128; t++) s += sKf[t*SFT + tid];
        g_S[base + 8192 + tid] = s;
    }
}

// ---------------------------------------------------------------------------
// Kernel D: per-chunk output. 1024 threads. Inline MLP-7 prefix reduction;
// V staged via cp.async (rounded in-place after wait).
// ---------------------------------------------------------------------------
__global__ __launch_bounds__(1024, 1) void attn_out_kernel(
        const float* __restrict__ pw, const float* __restrict__ pb,
        const float* __restrict__ coeff, float* __restrict__ out) {
    extern __shared__ __align__(16) float smD[];
    float* sQT   = smD;
    float* sKT   = smD + 17408;
    float* sV    = smD + 34816;
    float* sP    = smD + 44032;
    float* sPden = smD + 53248;
    float* sDen  = smD + 53376;
    float* sCB   = smD + 53504;
    float* sSB   = smD + 53568;

    const int nh = blockIdx.x, c = blockIdx.y;
    const int n = nh >> 3, h = nh & 7;
    const int tid = threadIdx.x;
    const int wid = tid >> 5, lane = tid & 31;
    const int gid = lane >> 2, tid4 = lane & 3;

    // V via cp.async (overlaps with feature compute below)
    int vsm[2];
    {
        uint32_t sv = smem_u32(sV);
#pragma unroll
        for (int j = 0; j < 2; j++) {
            int idx = (tid + j * 1024) * 4;   // 4 floats per cp
            int t = idx >> 6, di = idx & 63;
            vsm[j] = t*SVE + di;
            CP_ASYNC16(sv + vsm[j]*4,
                       &g_V[((n << 10) + c * TCH + t) * DDIM + (h << 6) + di]);
        }
        CP_COMMIT();
    }

    if (tid < 128) sDen[tid] = 0.0f;
    if (tid >= 128 && tid < 192) {
        int di = tid - 128;
        float sb_, cb_;
        sincosf(pb[(h << 6) + di], &sb_, &cb_);
        sCB[di] = cb_; sSB[di] = sb_;
    }
    __syncthreads();

    // Phase 1a: features (one accurate sincos per element + bias rotation)
    for (int idx = tid; idx < 128*64; idx += 1024) {
        int t = idx >> 6, di = idx & 63;
        int tg = c * TCH + t;
        int gbase = ((n << 10) + tg) * DDIM + (h << 6) + di;
        float qv = g_Q[gbase], kv = g_K[gbase];
        float w  = pw[(h << 6) + di];
        float cf = coeff[(h << 6) + di];
        float sk, ck;
        sincosf((float)tg * w, &sk, &ck);
        float cb_ = sCB[di], sb_ = sSB[di];
        float cq = ck * cb_ - sk * sb_;
        float sq = sk * cb_ + ck * sb_;
        float qc = qv * cf;
        sQT[di*SFT + t]        = f2tf_f(qc * cq);
        sQT[(64 + di)*SFT + t] = f2tf_f(qc * sq);
        sKT[di*SFT + t]        = f2tf_f(kv * ck);
        sKT[(64 + di)*SFT + t] = f2tf_f(kv * sk);
    }
    // Phase 1b: inline prefix reduction over chunk states (MLP=7 batched)
    if (c > 0) {
        size_t sb = (size_t)nh * NCH * SROW;
        for (int idx = tid; idx < SROW; idx += 1024) {
            float v0 = g_S[sb + 0*SROW + idx];
            float v1 = g_S[sb + 1*SROW + idx];
            float v2 = g_S[sb + 2*SROW + idx];
            float v3 = g_S[sb + 3*SROW + idx];
            float v4 = g_S[sb + 4*SROW + idx];
            float v5 = g_S[sb + 5*SROW + idx];
            float v6 = g_S[sb + 6*SROW + idx];
            float a = v0;
            if (c > 1) a += v1;
            if (c > 2) a += v2;
            if (c > 3) a += v3;
            if (c > 4) a += v4;
            if (c > 5) a += v5;
            if (c > 6) a += v6;
            if (idx < 8192) sP[(idx >> 6)*SVE + (idx & 63)] = f2tf_f(a);
            else            sPden[idx - 8192] = a;
        }
    }
    CP_WAIT(0);
    // Round own V elements in place (rna; restores accuracy margin)
#pragma unroll
    for (int j = 0; j < 2; j++) {
        float4 v = *(float4*)&sV[vsm[j]];
        v.x = f2tf_f(v.x); v.y = f2tf_f(v.y);
        v.z = f2tf_f(v.z); v.w = f2tf_f(v.w);
        *(float4*)&sV[vsm[j]] = v;
    }
    __syncthreads();

    const uint32_t* sQT32 = (const uint32_t*)sQT;
    const uint32_t* sKT32 = (const uint32_t*)sKT;
    const uint32_t* sV32  = (const uint32_t*)sV;
    const uint32_t* sP32  = (const uint32_t*)sP;

    // Phase 2: scores (128x128, k = feature 128), 32 warps, warp tile 32x16
    const int m2 = (wid & 3) * 32;
    const int n2 = (wid >> 2) * 16;
    float acc[2][2][4] = {};
#pragma unroll
    for (int k8 = 0; k8 < 16; k8++) {
        const int kk = k8 * 8 + tid4;
        uint32_t af[2][4];
#pragma unroll
        for (int mt = 0; mt < 2; mt++) {
            int r = m2 + mt * 16 + gid;
            af[mt][0] = sQT32[kk*SFT + r];
            af[mt][1] = sQT32[kk*SFT + r + 8];
            af[mt][2] = sQT32[(kk+4)*SFT + r];
            af[mt][3] = sQT32[(kk+4)*SFT + r + 8];
        }
        uint32_t bf[2][2];
#pragma unroll
        for (int nt = 0; nt < 2; nt++) {
            int nn = n2 + nt * 8 + gid;
            bf[nt][0] = sKT32[kk*SFT + nn];
            bf[nt][1] = sKT32[(kk+4)*SFT + nn];
        }
#pragma unroll
        for (int mt = 0; mt < 2; mt++)
#pragma unroll
            for (int nt = 0; nt < 2; nt++)
                mma_tf32(acc[mt][nt], af[mt], bf[nt]);
    }
    __syncthreads();   // all warps done reading sKT

    // Causal mask -> write transposed sAT[col][row] (round at store), row sums
    float* sAT = sKT;
#pragma unroll
    for (int mt = 0; mt < 2; mt++) {
        int r = m2 + mt * 16 + gid;
        float rs_lo = 0.0f, rs_hi = 0.0f;
#pragma unroll
        for (int nt = 0; nt < 2; nt++) {
            int cb = n2 + nt * 8 + tid4 * 2;
            float v0 = (cb     <= r)     ? acc[mt][nt][0] : 0.0f;
            float v1 = (cb + 1 <= r)     ? acc[mt][nt][1] : 0.0f;
            float v2 = (cb     <= r + 8) ? acc[mt][nt][2] : 0.0f;
            float v3 = (cb + 1 <= r + 8) ? acc[mt][nt][3] : 0.0f;
            sAT[cb * SFT + r]           = f2tf_f(v0);
            sAT[(cb + 1) * SFT + r]     = f2tf_f(v1);
            sAT[cb * SFT + r + 8]       = f2tf_f(v2);
            sAT[(cb + 1) * SFT + r + 8] = f2tf_f(v3);
            rs_lo += v0 + v1;
            rs_hi += v2 + v3;
        }
        atomicAdd(&sDen[r], rs_lo);
        atomicAdd(&sDen[r + 8], rs_hi);
    }
    __syncthreads();

    const uint32_t* sAT32 = (const uint32_t*)sAT;

    // Phase 3: out = A@V + PhiQ^T@P  (128x64), 32 warps, warp tile 16x16
    const int m3 = (wid & 7) * 16;
    const int n3 = (wid >> 3) * 16;
    float o[2][4] = {};
#pragma unroll
    for (int k8 = 0; k8 < 16; k8++) {
        const int kk = k8 * 8 + tid4;
        uint32_t af[4];
        {
            int r = m3 + gid;
            af[0] = sAT32[kk*SFT + r];
            af[1] = sAT32[kk*SFT + r + 8];
            af[2] = sAT32[(kk+4)*SFT + r];
            af[3] = sAT32[(kk+4)*SFT + r + 8];
        }
        uint32_t bf[2][2];
#pragma unroll
        for (int nt = 0; nt < 2; nt++) {
            int nn = n3 + nt * 8 + gid;
            bf[nt][0] = sV32[kk*SVE + nn];
            bf[nt][1] = sV32[(kk+4)*SVE + nn];
        }
#pragma unroll
        for (int nt = 0; nt < 2; nt++)
            mma_tf32(o[nt], af, bf[nt]);
    }
    if (c > 0) {
#pragma unroll
        for (int k8 = 0; k8 < 16; k8++) {
            const int kk = k8 * 8 + tid4;
            uint32_t af[4];
            {
                int r = m3 + gid;
                af[0] = sQT32[kk*SFT + r];
                af[1] = sQT32[kk*SFT + r + 8];
                af[2] = sQT32[(kk+4)*SFT + r];
                af[3] = sQT32[(kk+4)*SFT + r + 8];
            }
            uint32_t bf[2][2];
#pragma unroll
            for (int nt = 0; nt < 2; nt++) {
                int nn = n3 + nt * 8 + gid;
                bf[nt][0] = sP32[kk*SVE + nn];
                bf[nt][1] = sP32[(kk+4)*SVE + nn];
            }
#pragma unroll
            for (int nt = 0; nt < 2; nt++)
                mma_tf32(o[nt], af, bf[nt]);
        }
        // den inter-chunk term (fp32, 8-way split over f)
        int t = tid & 127, part = tid >> 7;
        float s = 0.0f;
        for (int f = part * 16; f < part * 16 + 16; f++)
            s += sQT[f*SFT + t] * sPden[f];
        atomicAdd(&sDen[t], s);
    }
    __syncthreads();

    // Phase 4: normalize + write (N, Lq, H*dh)
    {
        int r = m3 + gid;
        float inv_lo = 1.0f / sDen[r];
        float inv_hi = 1.0f / sDen[r + 8];
        int tg_lo = c * TCH + r;
        int tg_hi = tg_lo + 8;
#pragma unroll
        for (int nt = 0; nt < 2; nt++) {
            int e = n3 + nt * 8 + tid4 * 2;
            *(float2*)&out[((n << 10) + tg_lo) * DDIM + (h << 6) + e] =
                make_float2(o[nt][0] * inv_lo, o[nt][1] * inv_lo);
            *(float2*)&out[((n << 10) + tg_hi) * DDIM + (h << 6) + e] =
                make_float2(o[nt][2] * inv_hi, o[nt][3] * inv_hi);
        }
    }
}

// ---------------------------------------------------------------------------
extern "C" void kernel_launch(void* const* d_in, const int* in_sizes, int n_in,
                              void* d_out, int out_size) {
    const float* query = (const float*)d_in[0];
    const float* key   = (const float*)d_in[1];
    const float* Wq    = (const float*)d_in[2];
    const float* Wk    = (const float*)d_in[3];
    const float* Wv    = (const float*)d_in[4];
    const float* coeff = (const float*)d_in[5];
    const float* pw    = (const float*)d_in[6];
    const float* pb    = (const float*)d_in[7];
    float* out = (float*)d_out;

    cudaFuncSetAttribute(proj_mma_kernel,
                         cudaFuncAttributeMaxDynamicSharedMemorySize, 49152);
    cudaFuncSetAttribute(chunk_state_kernel,
                         cudaFuncAttributeMaxDynamicSharedMemorySize, 107520);
    cudaFuncSetAttribute(attn_out_kernel,
                         cudaFuncAttributeMaxDynamicSharedMemorySize, 214528);

    conv_tf32_kernel<<<dim3(DDIM*DDIM/4/256, 3), 256>>>(Wq, Wk, Wv);
    proj_mma_kernel<<<dim3(MROWS/128, DDIM/64, 3), 128, 49152>>>(query, key);
    chunk_state_kernel<<<dim3(NHH, NCH-1), 512, 107520>>>(pw);
    attn_out_kernel<<<dim3(NHH, NCH), 1024, 214528>>>(pw, pb, coeff, out);
}

// round 13
// speedup vs baseline: 1.3457x; 1.2176x over previous
#include <cuda_runtime.h>
#include <math.h>
#include <stdint.h>

// Problem constants
#define NB   2
#define LSEQ 1024
#define HH   8
#define DHD  64
#define DDIM 512
#define TCH  128
#define NCH  8
#define NHH  16
#define MROWS (NB*LSEQ)    // 2048
#define SROW 8320          // per-chunk state: 128x64 S + 128 den

// Device scratch (no cudaMalloc allowed)
__device__ float g_Q[MROWS*DDIM];
__device__ float g_K[MROWS*DDIM];
__device__ float g_V[MROWS*DDIM];
__device__ float g_S[NHH*NCH*SROW];
// tf32-pre-rounded weights
__device__ float g_cWq[DDIM*DDIM];
__device__ float g_cWk[DDIM*DDIM];
__device__ float g_cWv[DDIM*DDIM];

__device__ __forceinline__ float softplus_f(float x) {
    return fmaxf(x, 0.0f) + log1pf(expf(-fabsf(x)));
}

// ---------------------------------------------------------------------------
// Primitives (compile clean for compute_103 baseline target)
// ---------------------------------------------------------------------------
__device__ __forceinline__ uint32_t smem_u32(const void* p) {
    uint32_t a;
    asm("{ .reg .u64 t; cvta.to.shared.u64 t, %1; cvt.u32.u64 %0, t; }"
        : "=r"(a) : "l"(p));
    return a;
}
#define CP_ASYNC16(dst, src) \
    asm volatile("cp.async.cg.shared.global [%0], [%1], 16;" :: "r"(dst), "l"(src))
#define CP_COMMIT()  asm volatile("cp.async.commit_group;" ::: "memory")
#define CP_WAIT(n)   asm volatile("cp.async.wait_group %0;" :: "n"(n) : "memory")

__device__ __forceinline__ void mma_tf32(float* d, const uint32_t* a, const uint32_t* b) {
    asm volatile(
        "mma.sync.aligned.m16n8k8.row.col.f32.tf32.tf32.f32 "
        "{%0,%1,%2,%3}, {%4,%5,%6,%7}, {%8,%9}, {%0,%1,%2,%3};"
        : "+f"(d[0]), "+f"(d[1]), "+f"(d[2]), "+f"(d[3])
        : "r"(a[0]), "r"(a[1]), "r"(a[2]), "r"(a[3]), "r"(b[0]), "r"(b[1]));
}
// round-to-nearest fp32 -> tf32 bits, returned as float bit-pattern
__device__ __forceinline__ float f2tf_f(float x) {
    uint32_t r;
    asm("cvt.rna.tf32.f32 %0, %1;" : "=r"(r) : "f"(x));
    return __uint_as_float(r);
}
// swizzle for proj smem: k column xor'd by row&7 (units of 4 floats)
__device__ __forceinline__ int swz(int row, int k) { return k ^ ((row & 7) << 2); }

// Padded strides (==8 mod 32 -> column-pattern fragment LDS conflict-free)
#define SFT 136
#define SVE 72

// ---------------------------------------------------------------------------
// Kernel 0: round weights to tf32 (rna) once. y: 0=Wq, 1=Wk, 2=Wv
// ---------------------------------------------------------------------------
__global__ __launch_bounds__(256) void conv_tf32_kernel(
        const float* __restrict__ Wq, const float* __restrict__ Wk,
        const float* __restrict__ Wv) {
    const int y = blockIdx.y;
    const float* src = (y == 0) ? Wq : (y == 1) ? Wk : Wv;
    float* dst = (y == 0) ? g_cWq : (y == 1) ? g_cWk : g_cWv;
    int idx = blockIdx.x * 256 + threadIdx.x;
    if (idx < DDIM*DDIM/4) {
        float4 v = ((const float4*)src)[idx];
        v.x = f2tf_f(v.x); v.y = f2tf_f(v.y);
        v.z = f2tf_f(v.z); v.w = f2tf_f(v.w);
        ((float4*)dst)[idx] = v;
    }
}

// ---------------------------------------------------------------------------
// Kernel G: projection GEMM, warp tf32 mma. Block tile 128x64, 4 warps
// (warp 64x32), BK=32, 3-stage cp.async ring (issue depth 2) -> 72KB smem,
// 3 blocks/SM. Loads get 2 compute-stages of latency cover.
// ---------------------------------------------------------------------------
__global__ __launch_bounds__(128, 3) void proj_mma_kernel(
        const float* __restrict__ query, const float* __restrict__ key) {
    extern __shared__ __align__(16) float sm[];
    // stage s: A at sm + s*6144 (128x32), B at sm + s*6144 + 4096 (64x32)

    const int which = blockIdx.z;
    const float* __restrict__ A = (which == 0) ? query : key;
    const float* __restrict__ B = (which == 0) ? g_cWq : (which == 1) ? g_cWk : g_cWv;
    float* __restrict__ out = (which == 0) ? g_Q : (which == 1) ? g_K : g_V;
    const int am0 = blockIdx.x * 128;
    const int bn0 = blockIdx.y * 64;

    const int tid = threadIdx.x;
    const int wid = tid >> 5, lane = tid & 31;
    const int gid = lane >> 2, tid4 = lane & 3;
    const int m0 = (wid & 1) * 64;   // 2 m-tiles of 64
    const int n0 = (wid >> 1) * 32;  // 2 n-tiles of 32

    float acc[4][4][4];
#pragma unroll
    for (int i = 0; i < 4; i++)
#pragma unroll
        for (int j = 0; j < 4; j++)
#pragma unroll
            for (int q = 0; q < 4; q++) acc[i][j][q] = 0.0f;

    auto issue_stage = [&](int kt, int buf) {
        const int k0 = kt * 32;
        uint32_t sa = smem_u32(sm + buf * 6144);
        uint32_t sb = sa + 4096 * 4;
#pragma unroll
        for (int i = 0; i < 8; i++) {
            int f4 = tid + 128 * i;
            int row = f4 >> 3;
            int k4  = (f4 & 7) << 2;
            int soff = (row * 32 + swz(row, k4)) * 4;
            CP_ASYNC16(sa + soff, &A[(size_t)(am0 + row) * DDIM + k0 + k4]);
        }
#pragma unroll
        for (int i = 0; i < 4; i++) {
            int f4 = tid + 128 * i;
            int row = f4 >> 3;
            int k4  = (f4 & 7) << 2;
            int soff = (row * 32 + swz(row, k4)) * 4;
            CP_ASYNC16(sb + soff, &B[(size_t)(bn0 + row) * DDIM + k0 + k4]);
        }
        CP_COMMIT();
    };

    issue_stage(0, 0);
    issue_stage(1, 1);

    int buf = 0;
    for (int kt = 0; kt < 16; kt++) {
        if (kt < 14) issue_stage(kt + 2, (kt + 2) % 3);
        CP_WAIT(2);
        __syncthreads();

        const uint32_t* sA32 = (const uint32_t*)(sm + buf * 6144);
        const uint32_t* sB32 = sA32 + 4096;
#pragma unroll
        for (int k8 = 0; k8 < 4; k8++) {
            const int kk = k8 * 8 + tid4;
            uint32_t af[4][4];
#pragma unroll
            for (int mt = 0; mt < 4; mt++) {
                int r = m0 + mt * 16 + gid;
                af[mt][0] = sA32[r * 32 + swz(r, kk)];
                af[mt][1] = sA32[(r + 8) * 32 + swz(r + 8, kk)];
                af[mt][2] = sA32[r * 32 + swz(r, kk + 4)];
                af[mt][3] = sA32[(r + 8) * 32 + swz(r + 8, kk + 4)];
            }
            uint32_t bf[4][2];
#pragma unroll
            for (int nt = 0; nt < 4; nt++) {
                int nn = n0 + nt * 8 + gid;
                bf[nt][0] = sB32[nn * 32 + swz(nn, kk)];
                bf[nt][1] = sB32[nn * 32 + swz(nn, kk + 4)];
            }
#pragma unroll
            for (int mt = 0; mt < 4; mt++)
#pragma unroll
                for (int nt = 0; nt < 4; nt++)
                    mma_tf32(acc[mt][nt], af[mt], bf[nt]);
        }
        __syncthreads();
        buf = (buf + 1 == 3) ? 0 : buf + 1;
    }

    const bool act = (which < 2);
#pragma unroll
    for (int mt = 0; mt < 4; mt++) {
#pragma unroll
        for (int nt = 0; nt < 4; nt++) {
            int row = am0 + m0 + mt * 16 + gid;
            int col = bn0 + n0 + nt * 8 + tid4 * 2;
            float v0 = acc[mt][nt][0], v1 = acc[mt][nt][1];
            float v2 = acc[mt][nt][2], v3 = acc[mt][nt][3];
            if (act) {
                v0 = softplus_f(v0); v1 = softplus_f(v1);
                v2 = softplus_f(v2); v3 = softplus_f(v3);
            }
            *(float2*)&out[(size_t)row * DDIM + col] = make_float2(v0, v1);
            *(float2*)&out[(size_t)(row + 8) * DDIM + col] = make_float2(v2, v3);
        }
    }
}

// ---------------------------------------------------------------------------
// Kernel B: per-chunk KV state via warp mma. 512 threads, 16 warps,
// warp tile 32x16. No atomics. Chunks 0..6 only (7 unused).
// ---------------------------------------------------------------------------
__global__ __launch_bounds__(512) void chunk_state_kernel(const float* __restrict__ pw) {
    extern __shared__ __align__(16) float smB[];
    float* sKf = smB;                // [t][f] stride SFT
    float* sV  = smB + 128*SFT;      // [t][e] stride SVE

    const int nh = blockIdx.x, c = blockIdx.y;
    const int n = nh >> 3, h = nh & 7;
    const int tid = threadIdx.x;
    const int wid = tid >> 5, lane = tid & 31;
    const int gid = lane >> 2, tid4 = lane & 3;

    for (int idx = tid; idx < 128*64; idx += 512) {
        int t = idx >> 6, di = idx & 63;
        int tg = c * TCH + t;
        int gbase = ((n << 10) + tg) * DDIM + (h << 6) + di;
        float kv = g_K[gbase];
        float vv = g_V[gbase];
        float w  = pw[(h << 6) + di];
        float s, cs;
        sincosf((float)tg * w, &s, &cs);
        sKf[t*SFT + di]      = f2tf_f(kv * cs);
        sKf[t*SFT + 64 + di] = f2tf_f(kv * s);
        sV[t*SVE + di]       = f2tf_f(vv);
    }
    __syncthreads();

    const uint32_t* sKf32 = (const uint32_t*)sKf;
    const uint32_t* sV32  = (const uint32_t*)sV;
    const int m0 = (wid & 3) * 32;
    const int n0 = (wid >> 2) * 16;
    float acc[2][2][4] = {};
#pragma unroll
    for (int k8 = 0; k8 < 16; k8++) {
        const int kk = k8 * 8 + tid4;
        uint32_t af[2][4];
#pragma unroll
        for (int mt = 0; mt < 2; mt++) {
            int r = m0 + mt * 16 + gid;
            af[mt][0] = sKf32[kk*SFT + r];
            af[mt][1] = sKf32[kk*SFT + r + 8];
            af[mt][2] = sKf32[(kk+4)*SFT + r];
            af[mt][3] = sKf32[(kk+4)*SFT + r + 8];
        }
        uint32_t bf[2][2];
#pragma unroll
        for (int nt = 0; nt < 2; nt++) {
            int nn = n0 + nt * 8 + gid;
            bf[nt][0] = sV32[kk*SVE + nn];
            bf[nt][1] = sV32[(kk+4)*SVE + nn];
        }
#pragma unroll
        for (int mt = 0; mt < 2; mt++)
#pragma unroll
            for (int nt = 0; nt < 2; nt++)
                mma_tf32(acc[mt][nt], af[mt], bf[nt]);
    }
    size_t base = (size_t)(nh * NCH + c) * SROW;
#pragma unroll
    for (int mt = 0; mt < 2; mt++) {
#pragma unroll
        for (int nt = 0; nt < 2; nt++) {
            int f = m0 + mt * 16 + gid;
            int e = n0 + nt * 8 + tid4 * 2;
            *(float2*)&g_S[base + (size_t)f * 64 + e] =
                make_float2(acc[mt][nt][0], acc[mt][nt][1]);
            *(float2*)&g_S[base + (size_t)(f + 8) * 64 + e] =
                make_float2(acc[mt][nt][2], acc[mt][nt][3]);
        }
    }
    if (tid < 128) {
        float s = 0.0f;
        for (int t = 0; t < 128; t++) s += sKf[t*SFT + tid];
        g_S[base + 8192 + tid] = s;
    }
}

// ---------------------------------------------------------------------------
// Kernel D: per-chunk output. 1024 threads. Inline MLP-7 prefix reduction;
// V staged via cp.async (rounded in-place after wait).
// ---------------------------------------------------------------------------
__global__ __launch_bounds__(1024, 1) void attn_out_kernel(
        const float* __restrict__ pw, const float* __restrict__ pb,
        const float* __restrict__ coeff, float* __restrict__ out) {
    extern __shared__ __align__(16) float smD[];
    float* sQT   = smD;
    float* sKT   = smD + 17408;
    float* sV    = smD + 34816;
    float* sP    = smD + 44032;
    float* sPden = smD + 53248;
    float* sDen  = smD + 53376;
    float* sCB   = smD + 53504;
    float* sSB   = smD + 53568;

    const int nh = blockIdx.x, c = blockIdx.y;
    const int n = nh >> 3, h = nh & 7;
    const int tid = threadIdx.x;
    const int wid = tid >> 5, lane = tid & 31;
    const int gid = lane >> 2, tid4 = lane & 3;

    // V via cp.async (overlaps with feature compute below)
    int vsm[2];
    {
        uint32_t sv = smem_u32(sV);
#pragma unroll
        for (int j = 0; j < 2; j++) {
            int idx = (tid + j * 1024) * 4;   // 4 floats per cp
            int t = idx >> 6, di = idx & 63;
            vsm[j] = t*SVE + di;
            CP_ASYNC16(sv + vsm[j]*4,
                       &g_V[((n << 10) + c * TCH + t) * DDIM + (h << 6) + di]);
        }
        CP_COMMIT();
    }

    if (tid < 128) sDen[tid] = 0.0f;
    if (tid >= 128 && tid < 192) {
        int di = tid - 128;
        float sb_, cb_;
        sincosf(pb[(h << 6) + di], &sb_, &cb_);
        sCB[di] = cb_; sSB[di] = sb_;
    }
    __syncthreads();

    // Phase 1a: features (one accurate sincos per element + bias rotation)
    for (int idx = tid; idx < 128*64; idx += 1024) {
        int t = idx >> 6, di = idx & 63;
        int tg = c * TCH + t;
        int gbase = ((n << 10) + tg) * DDIM + (h << 6) + di;
        float qv = g_Q[gbase], kv = g_K[gbase];
        float w  = pw[(h << 6) + di];
        float cf = coeff[(h << 6) + di];
        float sk, ck;
        sincosf((float)tg * w, &sk, &ck);
        float cb_ = sCB[di], sb_ = sSB[di];
        float cq = ck * cb_ - sk * sb_;
        float sq = sk * cb_ + ck * sb_;
        float qc = qv * cf;
        sQT[di*SFT + t]        = f2tf_f(qc * cq);
        sQT[(64 + di)*SFT + t] = f2tf_f(qc * sq);
        sKT[di*SFT + t]        = f2tf_f(kv * ck);
        sKT[(64 + di)*SFT + t] = f2tf_f(kv * sk);
    }
    // Phase 1b: inline prefix reduction over chunk states (MLP=7 batched)
    if (c > 0) {
        size_t sb = (size_t)nh * NCH * SROW;
        for (int idx = tid; idx < SROW; idx += 1024) {
            float v0 = g_S[sb + 0*SROW + idx];
            float v1 = g_S[sb + 1*SROW + idx];
            float v2 = g_S[sb + 2*SROW + idx];
            float v3 = g_S[sb + 3*SROW + idx];
            float v4 = g_S[sb + 4*SROW + idx];
            float v5 = g_S[sb + 5*SROW + idx];
            float v6 = g_S[sb + 6*SROW + idx];
            float a = v0;
            if (c > 1) a += v1;
            if (c > 2) a += v2;
            if (c > 3) a += v3;
            if (c > 4) a += v4;
            if (c > 5) a += v5;
            if (c > 6) a += v6;
            if (idx < 8192) sP[(idx >> 6)*SVE + (idx & 63)] = f2tf_f(a);
            else            sPden[idx - 8192] = a;
        }
    }
    CP_WAIT(0);
    // Round own V elements in place (rna; preserves accuracy margin)
#pragma unroll
    for (int j = 0; j < 2; j++) {
        float4 v = *(float4*)&sV[vsm[j]];
        v.x = f2tf_f(v.x); v.y = f2tf_f(v.y);
        v.z = f2tf_f(v.z); v.w = f2tf_f(v.w);
        *(float4*)&sV[vsm[j]] = v;
    }
    __syncthreads();

    const uint32_t* sQT32 = (const uint32_t*)sQT;
    const uint32_t* sKT32 = (const uint32_t*)sKT;
    const uint32_t* sV32  = (const uint32_t*)sV;
    const uint32_t* sP32  = (const uint32_t*)sP;

    // Phase 2: scores (128x128, k = feature 128), 32 warps, warp tile 32x16
    const int m2 = (wid & 3) * 32;
    const int n2 = (wid >> 2) * 16;
    float acc[2][2][4] = {};
#pragma unroll
    for (int k8 = 0; k8 < 16; k8++) {
        const int kk = k8 * 8 + tid4;
        uint32_t af[2][4];
#pragma unroll
        for (int mt = 0; mt < 2; mt++) {
            int r = m2 + mt * 16 + gid;
            af[mt][0] = sQT32[kk*SFT + r];
            af[mt][1] = sQT32[kk*SFT + r + 8];
            af[mt][2] = sQT32[(kk+4)*SFT + r];
            af[mt][3] = sQT32[(kk+4)*SFT + r + 8];
        }
        uint32_t bf[2][2];
#pragma unroll
        for (int nt = 0; nt < 2; nt++) {
            int nn = n2 + nt * 8 + gid;
            bf[nt][0] = sKT32[kk*SFT + nn];
            bf[nt][1] = sKT32[(kk+4)*SFT + nn];
        }
#pragma unroll
        for (int mt = 0; mt < 2; mt++)
#pragma unroll
            for (int nt = 0; nt < 2; nt++)
                mma_tf32(acc[mt][nt], af[mt], bf[nt]);
    }
    __syncthreads();   // all warps done reading sKT

    // Causal mask -> write transposed sAT[col][row] (round at store), row sums
    float* sAT = sKT;
#pragma unroll
    for (int mt = 0; mt < 2; mt++) {
        int r = m2 + mt * 16 + gid;
        float rs_lo = 0.0f, rs_hi = 0.0f;
#pragma unroll
        for (int nt = 0; nt < 2; nt++) {
            int cb = n2 + nt * 8 + tid4 * 2;
            float v0 = (cb     <= r)     ? acc[mt][nt][0] : 0.0f;
            float v1 = (cb + 1 <= r)     ? acc[mt][nt][1] : 0.0f;
            float v2 = (cb     <= r + 8) ? acc[mt][nt][2] : 0.0f;
            float v3 = (cb + 1 <= r + 8) ? acc[mt][nt][3] : 0.0f;
            sAT[cb * SFT + r]           = f2tf_f(v0);
            sAT[(cb + 1) * SFT + r]     = f2tf_f(v1);
            sAT[cb * SFT + r + 8]       = f2tf_f(v2);
            sAT[(cb + 1) * SFT + r + 8] = f2tf_f(v3);
            rs_lo += v0 + v1;
            rs_hi += v2 + v3;
        }
        atomicAdd(&sDen[r], rs_lo);
        atomicAdd(&sDen[r + 8], rs_hi);
    }
    __syncthreads();

    const uint32_t* sAT32 = (const uint32_t*)sAT;

    // Phase 3: out = A@V + PhiQ^T@P  (128x64), 32 warps, warp tile 16x16
    const int m3 = (wid & 7) * 16;
    const int n3 = (wid >> 3) * 16;
    float o[2][4] = {};
#pragma unroll
    for (int k8 = 0; k8 < 16; k8++) {
        const int kk = k8 * 8 + tid4;
        uint32_t af[4];
        {
            int r = m3 + gid;
            af[0] = sAT32[kk*SFT + r];
            af[1] = sAT32[kk*SFT + r + 8];
            af[2] = sAT32[(kk+4)*SFT + r];
            af[3] = sAT32[(kk+4)*SFT + r + 8];
        }
        uint32_t bf[2][2];
#pragma unroll
        for (int nt = 0; nt < 2; nt++) {
            int nn = n3 + nt * 8 + gid;
            bf[nt][0] = sV32[kk*SVE + nn];
            bf[nt][1] = sV32[(kk+4)*SVE + nn];
        }
#pragma unroll
        for (int nt = 0; nt < 2; nt++)
            mma_tf32(o[nt], af, bf[nt]);
    }
    if (c > 0) {
#pragma unroll
        for (int k8 = 0; k8 < 16; k8++) {
            const int kk = k8 * 8 + tid4;
            uint32_t af[4];
            {
                int r = m3 + gid;
                af[0] = sQT32[kk*SFT + r];
                af[1] = sQT32[kk*SFT + r + 8];
                af[2] = sQT32[(kk+4)*SFT + r];
                af[3] = sQT32[(kk+4)*SFT + r + 8];
            }
            uint32_t bf[2][2];
#pragma unroll
            for (int nt = 0; nt < 2; nt++) {
                int nn = n3 + nt * 8 + gid;
                bf[nt][0] = sP32[kk*SVE + nn];
                bf[nt][1] = sP32[(kk+4)*SVE + nn];
            }
#pragma unroll
            for (int nt = 0; nt < 2; nt++)
                mma_tf32(o[nt], af, bf[nt]);
        }
        // den inter-chunk term (fp32, 8-way split over f)
        int t = tid & 127, part = tid >> 7;
        float s = 0.0f;
        for (int f = part * 16; f < part * 16 + 16; f++)
            s += sQT[f*SFT + t] * sPden[f];
        atomicAdd(&sDen[t], s);
    }
    __syncthreads();

    // Phase 4: normalize + write (N, Lq, H*dh)
    {
        int r = m3 + gid;
        float inv_lo = 1.0f / sDen[r];
        float inv_hi = 1.0f / sDen[r + 8];
        int tg_lo = c * TCH + r;
        int tg_hi = tg_lo + 8;
#pragma unroll
        for (int nt = 0; nt < 2; nt++) {
            int e = n3 + nt * 8 + tid4 * 2;
            *(float2*)&out[((n << 10) + tg_lo) * DDIM + (h << 6) + e] =
                make_float2(o[nt][0] * inv_lo, o[nt][1] * inv_lo);
            *(float2*)&out[((n << 10) + tg_hi) * DDIM + (h << 6) + e] =
                make_float2(o[nt][2] * inv_hi, o[nt][3] * inv_hi);
        }
    }
}

// ---------------------------------------------------------------------------
extern "C" void kernel_launch(void* const* d_in, const int* in_sizes, int n_in,
                              void* d_out, int out_size) {
    const float* query = (const float*)d_in[0];
    const float* key   = (const float*)d_in[1];
    const float* Wq    = (const float*)d_in[2];
    const float* Wk    = (const float*)d_in[3];
    const float* Wv    = (const float*)d_in[4];
    const float* coeff = (const float*)d_in[5];
    const float* pw    = (const float*)d_in[6];
    const float* pb    = (const float*)d_in[7];
    float* out = (float*)d_out;

    cudaFuncSetAttribute(proj_mma_kernel,
                         cudaFuncAttributeMaxDynamicSharedMemorySize, 73728);
    cudaFuncSetAttribute(chunk_state_kernel,
                         cudaFuncAttributeMaxDynamicSharedMemorySize, 107520);
    cudaFuncSetAttribute(attn_out_kernel,
                         cudaFuncAttributeMaxDynamicSharedMemorySize, 214528);

    conv_tf32_kernel<<<dim3(DDIM*DDIM/4/256, 3), 256>>>(Wq, Wk, Wv);
    proj_mma_kernel<<<dim3(MROWS/128, DDIM/64, 3), 128, 73728>>>(query, key);
    chunk_state_kernel<<<dim3(NHH, NCH-1), 512, 107520>>>(pw);
    attn_out_kernel<<<dim3(NHH, NCH), 1024, 214528>>>(pw, pb, coeff, out);
}

// round 14
// speedup vs baseline: 1.5424x; 1.1462x over previous
#include <cuda_runtime.h>
#include <cuda_fp16.h>
#include <math.h>
#include <stdint.h>

// Problem constants
#define NB   2
#define LSEQ 1024
#define HH   8
#define DHD  64
#define DDIM 512
#define TCH  128
#define NCH  8
#define NHH  16
#define MROWS (NB*LSEQ)    // 2048
#define SROW 8320          // per-chunk state: 128x64 S + 128 den

// Device scratch (no cudaMalloc allowed)
__device__ float g_Q[MROWS*DDIM];
__device__ float g_K[MROWS*DDIM];
__device__ float g_V[MROWS*DDIM];
__device__ float g_S[NHH*NCH*SROW];
// fp16 copies for the projection GEMM
__device__ __half g_hq[MROWS*DDIM];
__device__ __half g_hk[MROWS*DDIM];
__device__ __half g_hWq[DDIM*DDIM];
__device__ __half g_hWk[DDIM*DDIM];
__device__ __half g_hWv[DDIM*DDIM];

__device__ __forceinline__ float softplus_f(float x) {
    return fmaxf(x, 0.0f) + log1pf(expf(-fabsf(x)));
}

// ---------------------------------------------------------------------------
// Primitives (compile clean for compute_103 baseline target)
// ---------------------------------------------------------------------------
__device__ __forceinline__ uint32_t smem_u32(const void* p) {
    uint32_t a;
    asm("{ .reg .u64 t; cvta.to.shared.u64 t, %1; cvt.u32.u64 %0, t; }"
        : "=r"(a) : "l"(p));
    return a;
}
#define CP_ASYNC16(dst, src) \
    asm volatile("cp.async.cg.shared.global [%0], [%1], 16;" :: "r"(dst), "l"(src))
#define CP_COMMIT()  asm volatile("cp.async.commit_group;" ::: "memory")
#define CP_WAIT(n)   asm volatile("cp.async.wait_group %0;" :: "n"(n) : "memory")

__device__ __forceinline__ void mma_tf32(float* d, const uint32_t* a, const uint32_t* b) {
    asm volatile(
        "mma.sync.aligned.m16n8k8.row.col.f32.tf32.tf32.f32 "
        "{%0,%1,%2,%3}, {%4,%5,%6,%7}, {%8,%9}, {%0,%1,%2,%3};"
        : "+f"(d[0]), "+f"(d[1]), "+f"(d[2]), "+f"(d[3])
        : "r"(a[0]), "r"(a[1]), "r"(a[2]), "r"(a[3]), "r"(b[0]), "r"(b[1]));
}
__device__ __forceinline__ void mma_f16(float* d, const uint32_t* a, const uint32_t* b) {
    asm volatile(
        "mma.sync.aligned.m16n8k16.row.col.f32.f16.f16.f32 "
        "{%0,%1,%2,%3}, {%4,%5,%6,%7}, {%8,%9}, {%0,%1,%2,%3};"
        : "+f"(d[0]), "+f"(d[1]), "+f"(d[2]), "+f"(d[3])
        : "r"(a[0]), "r"(a[1]), "r"(a[2]), "r"(a[3]), "r"(b[0]), "r"(b[1]));
}
// round-to-nearest fp32 -> tf32 bits, returned as float bit-pattern
__device__ __forceinline__ float f2tf_f(float x) {
    uint32_t r;
    asm("cvt.rna.tf32.f32 %0, %1;" : "=r"(r) : "f"(x));
    return __uint_as_float(r);
}
// half-layout swizzle (b32 units, 16 b32 per row): XOR bits 2-3 by row bits 1-2
__device__ __forceinline__ int hswz(int row, int c) { return c ^ (((row >> 1) & 3) << 2); }

// Padded strides for attention smem (==8 mod 32)
#define SFT 136
#define SVE 72

// ---------------------------------------------------------------------------
// Kernel 0: convert inputs to fp16 (rne). y: 0=query, 1=key, 2=Wq, 3=Wk, 4=Wv
// ---------------------------------------------------------------------------
__global__ __launch_bounds__(256) void conv_half_kernel(
        const float* __restrict__ query, const float* __restrict__ key,
        const float* __restrict__ Wq, const float* __restrict__ Wk,
        const float* __restrict__ Wv) {
    const int y = blockIdx.y;
    const float* src; __half* dst; int n4;
    switch (y) {
        case 0: src = query; dst = g_hq;  n4 = MROWS*DDIM/4; break;
        case 1: src = key;   dst = g_hk;  n4 = MROWS*DDIM/4; break;
        case 2: src = Wq;    dst = g_hWq; n4 = DDIM*DDIM/4;  break;
        case 3: src = Wk;    dst = g_hWk; n4 = DDIM*DDIM/4;  break;
        default: src = Wv;   dst = g_hWv; n4 = DDIM*DDIM/4;  break;
    }
    int idx = blockIdx.x * 256 + threadIdx.x;
    if (idx < n4) {
        float4 v = ((const float4*)src)[idx];
        __half2 h0 = __floats2half2_rn(v.x, v.y);
        __half2 h1 = __floats2half2_rn(v.z, v.w);
        uint2 pk;
        pk.x = *(uint32_t*)&h0;
        pk.y = *(uint32_t*)&h1;
        ((uint2*)dst)[idx] = pk;
    }
}

// ---------------------------------------------------------------------------
// Kernel G: projection GEMM in fp16 (m16n8k16). Block tile 128x64, 4 warps
// (warp 64x32), BK=32 halves, 4-stage cp.async ring (issue depth 3),
// 12KB/stage = 48KB smem -> 4 blocks/SM.
// ---------------------------------------------------------------------------
__global__ __launch_bounds__(128, 4) void proj_mma_kernel() {
    extern __shared__ __align__(16) uint32_t smP[];
    // stage s (3072 b32): A 128x16 b32 at +0, B 64x16 b32 at +2048

    const int which = blockIdx.z;
    const __half* __restrict__ A = (which == 0) ? g_hq : g_hk;
    const __half* __restrict__ B = (which == 0) ? g_hWq : (which == 1) ? g_hWk : g_hWv;
    float* __restrict__ out = (which == 0) ? g_Q : (which == 1) ? g_K : g_V;
    const int am0 = blockIdx.x * 128;
    const int bn0 = blockIdx.y * 64;

    const int tid = threadIdx.x;
    const int wid = tid >> 5, lane = tid & 31;
    const int gid = lane >> 2, tid4 = lane & 3;
    const int m0 = (wid & 1) * 64;
    const int n0 = (wid >> 1) * 32;

    float acc[4][4][4];
#pragma unroll
    for (int i = 0; i < 4; i++)
#pragma unroll
        for (int j = 0; j < 4; j++)
#pragma unroll
            for (int q = 0; q < 4; q++) acc[i][j][q] = 0.0f;

    const uint32_t sbase = smem_u32(smP);

    auto issue_stage = [&](int kt, int buf) {
        const int k0 = kt * 32;                 // in halves
        uint32_t sa = sbase + buf * 3072 * 4;
        uint32_t sb = sa + 2048 * 4;
#pragma unroll
        for (int i = 0; i < 4; i++) {           // A: 512 16B chunks
            int f4 = tid + 128 * i;
            int row = f4 >> 2;
            int cq  = (f4 & 3) << 2;            // b32 col of chunk
            int soff = (row * 16 + hswz(row, cq)) * 4;
            CP_ASYNC16(sa + soff, &A[(size_t)(am0 + row) * DDIM + k0 + cq * 2]);
        }
#pragma unroll
        for (int i = 0; i < 2; i++) {           // B: 256 16B chunks
            int f4 = tid + 128 * i;
            int row = f4 >> 2;
            int cq  = (f4 & 3) << 2;
            int soff = (row * 16 + hswz(row, cq)) * 4;
            CP_ASYNC16(sb + soff, &B[(size_t)(bn0 + row) * DDIM + k0 + cq * 2]);
        }
        CP_COMMIT();
    };

    issue_stage(0, 0);
    issue_stage(1, 1);
    issue_stage(2, 2);

    for (int kt = 0; kt < 16; kt++) {
        if (kt < 13) issue_stage(kt + 3, (kt + 3) & 3);
        CP_WAIT(3);
        __syncthreads();

        const uint32_t* sA = smP + (kt & 3) * 3072;
        const uint32_t* sB = sA + 2048;
#pragma unroll
        for (int step = 0; step < 2; step++) {  // two k16 steps per 32-half stage
            const int s8 = step * 8;
            uint32_t af[4][4];
#pragma unroll
            for (int mt = 0; mt < 4; mt++) {
                int r = m0 + mt * 16 + gid;
                af[mt][0] = sA[r * 16 + hswz(r, s8 + tid4)];
                af[mt][1] = sA[(r + 8) * 16 + hswz(r + 8, s8 + tid4)];
                af[mt][2] = sA[r * 16 + hswz(r, s8 + tid4 + 4)];
                af[mt][3] = sA[(r + 8) * 16 + hswz(r + 8, s8 + tid4 + 4)];
            }
            uint32_t bf[4][2];
#pragma unroll
            for (int nt = 0; nt < 4; nt++) {
                int nn = n0 + nt * 8 + gid;
                bf[nt][0] = sB[nn * 16 + hswz(nn, s8 + tid4)];
                bf[nt][1] = sB[nn * 16 + hswz(nn, s8 + tid4 + 4)];
            }
#pragma unroll
            for (int mt = 0; mt < 4; mt++)
#pragma unroll
                for (int nt = 0; nt < 4; nt++)
                    mma_f16(acc[mt][nt], af[mt], bf[nt]);
        }
        __syncthreads();
    }

    const bool act = (which < 2);
#pragma unroll
    for (int mt = 0; mt < 4; mt++) {
#pragma unroll
        for (int nt = 0; nt < 4; nt++) {
            int row = am0 + m0 + mt * 16 + gid;
            int col = bn0 + n0 + nt * 8 + tid4 * 2;
            float v0 = acc[mt][nt][0], v1 = acc[mt][nt][1];
            float v2 = acc[mt][nt][2], v3 = acc[mt][nt][3];
            if (act) {
                v0 = softplus_f(v0); v1 = softplus_f(v1);
                v2 = softplus_f(v2); v3 = softplus_f(v3);
            }
            *(float2*)&out[(size_t)row * DDIM + col] = make_float2(v0, v1);
            *(float2*)&out[(size_t)(row + 8) * DDIM + col] = make_float2(v2, v3);
        }
    }
}

// ---------------------------------------------------------------------------
// Kernel B: per-chunk KV state via warp tf32 mma (unchanged from r13).
// ---------------------------------------------------------------------------
__device__ __forceinline__ int swz(int row, int k) { return k ^ ((row & 7) << 2); }

__global__ __launch_bounds__(512) void chunk_state_kernel(const float* __restrict__ pw) {
    extern __shared__ __align__(16) float smB[];
    float* sKf = smB;                // [t][f] stride SFT
    float* sV  = smB + 128*SFT;      // [t][e] stride SVE

    const int nh = blockIdx.x, c = blockIdx.y;
    const int n = nh >> 3, h = nh & 7;
    const int tid = threadIdx.x;
    const int wid = tid >> 5, lane = tid & 31;
    const int gid = lane >> 2, tid4 = lane & 3;

    for (int idx = tid; idx < 128*64; idx += 512) {
        int t = idx >> 6, di = idx & 63;
        int tg = c * TCH + t;
        int gbase = ((n << 10) + tg) * DDIM + (h << 6) + di;
        float kv = g_K[gbase];
        float vv = g_V[gbase];
        float w  = pw[(h << 6) + di];
        float s, cs;
        sincosf((float)tg * w, &s, &cs);
        sKf[t*SFT + di]      = f2tf_f(kv * cs);
        sKf[t*SFT + 64 + di] = f2tf_f(kv * s);
        sV[t*SVE + di]       = f2tf_f(vv);
    }
    __syncthreads();

    const uint32_t* sKf32 = (const uint32_t*)sKf;
    const uint32_t* sV32  = (const uint32_t*)sV;
    const int m0 = (wid & 3) * 32;
    const int n0 = (wid >> 2) * 16;
    float acc[2][2][4] = {};
#pragma unroll
    for (int k8 = 0; k8 < 16; k8++) {
        const int kk = k8 * 8 + tid4;
        uint32_t af[2][4];
#pragma unroll
        for (int mt = 0; mt < 2; mt++) {
            int r = m0 + mt * 16 + gid;
            af[mt][0] = sKf32[kk*SFT + r];
            af[mt][1] = sKf32[kk*SFT + r + 8];
            af[mt][2] = sKf32[(kk+4)*SFT + r];
            af[mt][3] = sKf32[(kk+4)*SFT + r + 8];
        }
        uint32_t bf[2][2];
#pragma unroll
        for (int nt = 0; nt < 2; nt++) {
            int nn = n0 + nt * 8 + gid;
            bf[nt][0] = sV32[kk*SVE + nn];
            bf[nt][1] = sV32[(kk+4)*SVE + nn];
        }
#pragma unroll
        for (int mt = 0; mt < 2; mt++)
#pragma unroll
            for (int nt = 0; nt < 2; nt++)
                mma_tf32(acc[mt][nt], af[mt], bf[nt]);
    }
    size_t base = (size_t)(nh * NCH + c) * SROW;
#pragma unroll
    for (int mt = 0; mt < 2; mt++) {
#pragma unroll
        for (int nt = 0; nt < 2; nt++) {
            int f = m0 + mt * 16 + gid;
            int e = n0 + nt * 8 + tid4 * 2;
            *(float2*)&g_S[base + (size_t)f * 64 + e] =
                make_float2(acc[mt][nt][0], acc[mt][nt][1]);
            *(float2*)&g_S[base + (size_t)(f + 8) * 64 + e] =
                make_float2(acc[mt][nt][2], acc[mt][nt][3]);
        }
    }
    if (tid < 128) {
        float s = 0.0f;
        for (int t = 0; t < 128; t++) s += sKf[t*SFT + tid];
        g_S[base + 8192 + tid] = s;
    }
}

// ---------------------------------------------------------------------------
// Kernel D: per-chunk output (unchanged from r13). 1024 threads.
// ---------------------------------------------------------------------------
__global__ __launch_bounds__(1024, 1) void attn_out_kernel(
        const float* __restrict__ pw, const float* __restrict__ pb,
        const float* __restrict__ coeff, float* __restrict__ out) {
    extern __shared__ __align__(16) float smD[];
    float* sQT   = smD;
    float* sKT   = smD + 17408;
    float* sV    = smD + 34816;
    float* sP    = smD + 44032;
    float* sPden = smD + 53248;
    float* sDen  = smD + 53376;
    float* sCB   = smD + 53504;
    float* sSB   = smD + 53568;

    const int nh = blockIdx.x, c = blockIdx.y;
    const int n = nh >> 3, h = nh & 7;
    const int tid = threadIdx.x;
    const int wid = tid >> 5, lane = tid & 31;
    const int gid = lane >> 2, tid4 = lane & 3;

    // V via cp.async (overlaps with feature compute below)
    int vsm[2];
    {
        uint32_t sv = smem_u32(sV);
#pragma unroll
        for (int j = 0; j < 2; j++) {
            int idx = (tid + j * 1024) * 4;
            int t = idx >> 6, di = idx & 63;
            vsm[j] = t*SVE + di;
            CP_ASYNC16(sv + vsm[j]*4,
                       &g_V[((n << 10) + c * TCH + t) * DDIM + (h << 6) + di]);
        }
        CP_COMMIT();
    }

    if (tid < 128) sDen[tid] = 0.0f;
    if (tid >= 128 && tid < 192) {
        int di = tid - 128;
        float sb_, cb_;
        sincosf(pb[(h << 6) + di], &sb_, &cb_);
        sCB[di] = cb_; sSB[di] = sb_;
    }
    __syncthreads();

    // Phase 1a: features (one accurate sincos per element + bias rotation)
    for (int idx = tid; idx < 128*64; idx += 1024) {
        int t = idx >> 6, di = idx & 63;
        int tg = c * TCH + t;
        int gbase = ((n << 10) + tg) * DDIM + (h << 6) + di;
        float qv = g_Q[gbase], kv = g_K[gbase];
        float w  = pw[(h << 6) + di];
        float cf = coeff[(h << 6) + di];
        float sk, ck;
        sincosf((float)tg * w, &sk, &ck);
        float cb_ = sCB[di], sb_ = sSB[di];
        float cq = ck * cb_ - sk * sb_;
        float sq = sk * cb_ + ck * sb_;
        float qc = qv * cf;
        sQT[di*SFT + t]        = f2tf_f(qc * cq);
        sQT[(64 + di)*SFT + t] = f2tf_f(qc * sq);
        sKT[di*SFT + t]        = f2tf_f(kv * ck);
        sKT[(64 + di)*SFT + t] = f2tf_f(kv * sk);
    }
    // Phase 1b: inline prefix reduction over chunk states (MLP=7 batched)
    if (c > 0) {
        size_t sb = (size_t)nh * NCH * SROW;
        for (int idx = tid; idx < SROW; idx += 1024) {
            float v0 = g_S[sb + 0*SROW + idx];
            float v1 = g_S[sb + 1*SROW + idx];
            float v2 = g_S[sb + 2*SROW + idx];
            float v3 = g_S[sb + 3*SROW + idx];
            float v4 = g_S[sb + 4*SROW + idx];
            float v5 = g_S[sb + 5*SROW + idx];
            float v6 = g_S[sb + 6*SROW + idx];
            float a = v0;
            if (c > 1) a += v1;
            if (c > 2) a += v2;
            if (c > 3) a += v3;
            if (c > 4) a += v4;
            if (c > 5) a += v5;
            if (c > 6) a += v6;
            if (idx < 8192) sP[(idx >> 6)*SVE + (idx & 63)] = f2tf_f(a);
            else            sPden[idx - 8192] = a;
        }
    }
    CP_WAIT(0);
#pragma unroll
    for (int j = 0; j < 2; j++) {
        float4 v = *(float4*)&sV[vsm[j]];
        v.x = f2tf_f(v.x); v.y = f2tf_f(v.y);
        v.z = f2tf_f(v.z); v.w = f2tf_f(v.w);
        *(float4*)&sV[vsm[j]] = v;
    }
    __syncthreads();

    const uint32_t* sQT32 = (const uint32_t*)sQT;
    const uint32_t* sKT32 = (const uint32_t*)sKT;
    const uint32_t* sV32  = (const uint32_t*)sV;
    const uint32_t* sP32  = (const uint32_t*)sP;

    // Phase 2: scores (128x128, k = feature 128), 32 warps, warp tile 32x16
    const int m2 = (wid & 3) * 32;
    const int n2 = (wid >> 2) * 16;
    float acc[2][2][4] = {};
#pragma unroll
    for (int k8 = 0; k8 < 16; k8++) {
        const int kk = k8 * 8 + tid4;
        uint32_t af[2][4];
#pragma unroll
        for (int mt = 0; mt < 2; mt++) {
            int r = m2 + mt * 16 + gid;
            af[mt][0] = sQT32[kk*SFT + r];
            af[mt][1] = sQT32[kk*SFT + r + 8];
            af[mt][2] = sQT32[(kk+4)*SFT + r];
            af[mt][3] = sQT32[(kk+4)*SFT + r + 8];
        }
        uint32_t bf[2][2];
#pragma unroll
        for (int nt = 0; nt < 2; nt++) {
            int nn = n2 + nt * 8 + gid;
            bf[nt][0] = sKT32[kk*SFT + nn];
            bf[nt][1] = sKT32[(kk+4)*SFT + nn];
        }
#pragma unroll
        for (int mt = 0; mt < 2; mt++)
#pragma unroll
            for (int nt = 0; nt < 2; nt++)
                mma_tf32(acc[mt][nt], af[mt], bf[nt]);
    }
    __syncthreads();

    // Causal mask -> write transposed sAT[col][row] (round at store), row sums
    float* sAT = sKT;
#pragma unroll
    for (int mt = 0; mt < 2; mt++) {
        int r = m2 + mt * 16 + gid;
        float rs_lo = 0.0f, rs_hi = 0.0f;
#pragma unroll
        for (int nt = 0; nt < 2; nt++) {
            int cb = n2 + nt * 8 + tid4 * 2;
            float v0 = (cb     <= r)     ? acc[mt][nt][0] : 0.0f;
            float v1 = (cb + 1 <= r)     ? acc[mt][nt][1] : 0.0f;
            float v2 = (cb     <= r + 8) ? acc[mt][nt][2] : 0.0f;
            float v3 = (cb + 1 <= r + 8) ? acc[mt][nt][3] : 0.0f;
            sAT[cb * SFT + r]           = f2tf_f(v0);
            sAT[(cb + 1) * SFT + r]     = f2tf_f(v1);
            sAT[cb * SFT + r + 8]       = f2tf_f(v2);
            sAT[(cb + 1) * SFT + r + 8] = f2tf_f(v3);
            rs_lo += v0 + v1;
            rs_hi += v2 + v3;
        }
        atomicAdd(&sDen[r], rs_lo);
        atomicAdd(&sDen[r + 8], rs_hi);
    }
    __syncthreads();

    const uint32_t* sAT32 = (const uint32_t*)sAT;

    // Phase 3: out = A@V + PhiQ^T@P  (128x64), 32 warps, warp tile 16x16
    const int m3 = (wid & 7) * 16;
    const int n3 = (wid >> 3) * 16;
    float o[2][4] = {};
#pragma unroll
    for (int k8 = 0; k8 < 16; k8++) {
        const int kk = k8 * 8 + tid4;
        uint32_t af[4];
        {
            int r = m3 + gid;
            af[0] = sAT32[kk*SFT + r];
            af[1] = sAT32[kk*SFT + r + 8];
            af[2] = sAT32[(kk+4)*SFT + r];
            af[3] = sAT32[(kk+4)*SFT + r + 8];
        }
        uint32_t bf[2][2];
#pragma unroll
        for (int nt = 0; nt < 2; nt++) {
            int nn = n3 + nt * 8 + gid;
            bf[nt][0] = sV32[kk*SVE + nn];
            bf[nt][1] = sV32[(kk+4)*SVE + nn];
        }
#pragma unroll
        for (int nt = 0; nt < 2; nt++)
            mma_tf32(o[nt], af, bf[nt]);
    }
    if (c > 0) {
#pragma unroll
        for (int k8 = 0; k8 < 16; k8++) {
            const int kk = k8 * 8 + tid4;
            uint32_t af[4];
            {
                int r = m3 + gid;
                af[0] = sQT32[kk*SFT + r];
                af[1] = sQT32[kk*SFT + r + 8];
                af[2] = sQT32[(kk+4)*SFT + r];
                af[3] = sQT32[(kk+4)*SFT + r + 8];
            }
            uint32_t bf[2][2];
#pragma unroll
            for (int nt = 0; nt < 2; nt++) {
                int nn = n3 + nt * 8 + gid;
                bf[nt][0] = sP32[kk*SVE + nn];
                bf[nt][1] = sP32[(kk+4)*SVE + nn];
            }
#pragma unroll
            for (int nt = 0; nt < 2; nt++)
                mma_tf32(o[nt], af, bf[nt]);
        }
        int t = tid & 127, part = tid >> 7;
        float s = 0.0f;
        for (int f = part * 16; f < part * 16 + 16; f++)
            s += sQT[f*SFT + t] * sPden[f];
        atomicAdd(&sDen[t], s);
    }
    __syncthreads();

    // Phase 4: normalize + write (N, Lq, H*dh)
    {
        int r = m3 + gid;
        float inv_lo = 1.0f / sDen[r];
        float inv_hi = 1.0f / sDen[r + 8];
        int tg_lo = c * TCH + r;
        int tg_hi = tg_lo + 8;
#pragma unroll
        for (int nt = 0; nt < 2; nt++) {
            int e = n3 + nt * 8 + tid4 * 2;
            *(float2*)&out[((n << 10) + tg_lo) * DDIM + (h << 6) + e] =
                make_float2(o[nt][0] * inv_lo, o[nt][1] * inv_lo);
            *(float2*)&out[((n << 10) + tg_hi) * DDIM + (h << 6) + e] =
                make_float2(o[nt][2] * inv_hi, o[nt][3] * inv_hi);
        }
    }
}

// ---------------------------------------------------------------------------
extern "C" void kernel_launch(void* const* d_in, const int* in_sizes, int n_in,
                              void* d_out, int out_size) {
    const float* query = (const float*)d_in[0];
    const float* key   = (const float*)d_in[1];
    const float* Wq    = (const float*)d_in[2];
    const float* Wk    = (const float*)d_in[3];
    const float* Wv    = (const float*)d_in[4];
    const float* coeff = (const float*)d_in[5];
    const float* pw    = (const float*)d_in[6];
    const float* pb    = (const float*)d_in[7];
    float* out = (float*)d_out;

    cudaFuncSetAttribute(proj_mma_kernel,
                         cudaFuncAttributeMaxDynamicSharedMemorySize, 49152);
    cudaFuncSetAttribute(chunk_state_kernel,
                         cudaFuncAttributeMaxDynamicSharedMemorySize, 107520);
    cudaFuncSetAttribute(attn_out_kernel,
                         cudaFuncAttributeMaxDynamicSharedMemorySize, 214528);

    conv_half_kernel<<<dim3(1024, 5), 256>>>(query, key, Wq, Wk, Wv);
    proj_mma_kernel<<<dim3(MROWS/128, DDIM/64, 3), 128, 49152>>>();
    chunk_state_kernel<<<dim3(NHH, NCH-1), 512, 107520>>>(pw);
    attn_out_kernel<<<dim3(NHH, NCH), 1024, 214528>>>(pw, pb, coeff, out);
}

// round 15
// speedup vs baseline: 1.7981x; 1.1658x over previous
#include <cuda_runtime.h>
#include <cuda_fp16.h>
#include <math.h>
#include <stdint.h>

// Problem constants
#define NB   2
#define LSEQ 1024
#define HH   8
#define DHD  64
#define DDIM 512
#define TCH  128
#define NCH  8
#define NHH  16
#define MROWS (NB*LSEQ)    // 2048
#define SROW 8320          // per-chunk state: 128x64 S + 128 den

// Device scratch (no cudaMalloc allowed)
__device__ float g_Q[MROWS*DDIM];
__device__ float g_K[MROWS*DDIM];
__device__ float g_V[MROWS*DDIM];
__device__ float g_S[NHH*NCH*SROW];
// fp16 copies for the projection GEMM
__device__ __half g_hq[MROWS*DDIM];
__device__ __half g_hk[MROWS*DDIM];
__device__ __half g_hWq[DDIM*DDIM];
__device__ __half g_hWk[DDIM*DDIM];
__device__ __half g_hWv[DDIM*DDIM];

__device__ __forceinline__ float softplus_f(float x) {
    return fmaxf(x, 0.0f) + log1pf(expf(-fabsf(x)));
}

// ---------------------------------------------------------------------------
// Primitives (compile clean for compute_103 baseline target)
// ---------------------------------------------------------------------------
__device__ __forceinline__ uint32_t smem_u32(const void* p) {
    uint32_t a;
    asm("{ .reg .u64 t; cvta.to.shared.u64 t, %1; cvt.u32.u64 %0, t; }"
        : "=r"(a) : "l"(p));
    return a;
}
#define CP_ASYNC16(dst, src) \
    asm volatile("cp.async.cg.shared.global [%0], [%1], 16;" :: "r"(dst), "l"(src))
#define CP_COMMIT()  asm volatile("cp.async.commit_group;" ::: "memory")
#define CP_WAIT(n)   asm volatile("cp.async.wait_group %0;" :: "n"(n) : "memory")

__device__ __forceinline__ void mma_tf32(float* d, const uint32_t* a, const uint32_t* b) {
    asm volatile(
        "mma.sync.aligned.m16n8k8.row.col.f32.tf32.tf32.f32 "
        "{%0,%1,%2,%3}, {%4,%5,%6,%7}, {%8,%9}, {%0,%1,%2,%3};"
        : "+f"(d[0]), "+f"(d[1]), "+f"(d[2]), "+f"(d[3])
        : "r"(a[0]), "r"(a[1]), "r"(a[2]), "r"(a[3]), "r"(b[0]), "r"(b[1]));
}
__device__ __forceinline__ void mma_f16(float* d, const uint32_t* a, const uint32_t* b) {
    asm volatile(
        "mma.sync.aligned.m16n8k16.row.col.f32.f16.f16.f32 "
        "{%0,%1,%2,%3}, {%4,%5,%6,%7}, {%8,%9}, {%0,%1,%2,%3};"
        : "+f"(d[0]), "+f"(d[1]), "+f"(d[2]), "+f"(d[3])
        : "r"(a[0]), "r"(a[1]), "r"(a[2]), "r"(a[3]), "r"(b[0]), "r"(b[1]));
}
// round-to-nearest fp32 -> tf32 bits, returned as float bit-pattern
__device__ __forceinline__ float f2tf_f(float x) {
    uint32_t r;
    asm("cvt.rna.tf32.f32 %0, %1;" : "=r"(r) : "f"(x));
    return __uint_as_float(r);
}
__device__ __forceinline__ uint32_t pack_h2(float lo, float hi) {
    __half2 h = __floats2half2_rn(lo, hi);
    return *(uint32_t*)&h;
}
// half-layout swizzle (b32 units, 16 b32 per row): XOR bits 2-3 by row bits 1-2
__device__ __forceinline__ int hswz(int row, int c) { return c ^ (((row >> 1) & 3) << 2); }
// tf32 smem swizzle (proj-era)
__device__ __forceinline__ int swz(int row, int k) { return k ^ ((row & 7) << 2); }

// Strides
#define SFT 136   // chunk_state tf32 feature-major stride (floats)
#define SVE 72    // chunk_state value stride (floats)
#define SH  136   // attn fp16 pair-row stride (b32)
#define SVH 72    // attn fp16 value stride (b32)

// ---------------------------------------------------------------------------
// Kernel 0: convert inputs to fp16 (rne). y: 0=query, 1=key, 2=Wq, 3=Wk, 4=Wv
// ---------------------------------------------------------------------------
__global__ __launch_bounds__(256) void conv_half_kernel(
        const float* __restrict__ query, const float* __restrict__ key,
        const float* __restrict__ Wq, const float* __restrict__ Wk,
        const float* __restrict__ Wv) {
    const int y = blockIdx.y;
    const float* src; __half* dst; int n4;
    switch (y) {
        case 0: src = query; dst = g_hq;  n4 = MROWS*DDIM/4; break;
        case 1: src = key;   dst = g_hk;  n4 = MROWS*DDIM/4; break;
        case 2: src = Wq;    dst = g_hWq; n4 = DDIM*DDIM/4;  break;
        case 3: src = Wk;    dst = g_hWk; n4 = DDIM*DDIM/4;  break;
        default: src = Wv;   dst = g_hWv; n4 = DDIM*DDIM/4;  break;
    }
    int idx = blockIdx.x * 256 + threadIdx.x;
    if (idx < n4) {
        float4 v = ((const float4*)src)[idx];
        uint2 pk;
        pk.x = pack_h2(v.x, v.y);
        pk.y = pack_h2(v.z, v.w);
        ((uint2*)dst)[idx] = pk;
    }
}

// ---------------------------------------------------------------------------
// Kernel G: projection GEMM in fp16 (m16n8k16), 4-stage ring (as r14).
// ---------------------------------------------------------------------------
__global__ __launch_bounds__(128, 4) void proj_mma_kernel() {
    extern __shared__ __align__(16) uint32_t smP[];
    const int which = blockIdx.z;
    const __half* __restrict__ A = (which == 0) ? g_hq : g_hk;
    const __half* __restrict__ B = (which == 0) ? g_hWq : (which == 1) ? g_hWk : g_hWv;
    float* __restrict__ out = (which == 0) ? g_Q : (which == 1) ? g_K : g_V;
    const int am0 = blockIdx.x * 128;
    const int bn0 = blockIdx.y * 64;

    const int tid = threadIdx.x;
    const int wid = tid >> 5, lane = tid & 31;
    const int gid = lane >> 2, tid4 = lane & 3;
    const int m0 = (wid & 1) * 64;
    const int n0 = (wid >> 1) * 32;

    float acc[4][4][4];
#pragma unroll
    for (int i = 0; i < 4; i++)
#pragma unroll
        for (int j = 0; j < 4; j++)
#pragma unroll
            for (int q = 0; q < 4; q++) acc[i][j][q] = 0.0f;

    const uint32_t sbase = smem_u32(smP);

    auto issue_stage = [&](int kt, int buf) {
        const int k0 = kt * 32;
        uint32_t sa = sbase + buf * 3072 * 4;
        uint32_t sb = sa + 2048 * 4;
#pragma unroll
        for (int i = 0; i < 4; i++) {
            int f4 = tid + 128 * i;
            int row = f4 >> 2;
            int cq  = (f4 & 3) << 2;
            int soff = (row * 16 + hswz(row, cq)) * 4;
            CP_ASYNC16(sa + soff, &A[(size_t)(am0 + row) * DDIM + k0 + cq * 2]);
        }
#pragma unroll
        for (int i = 0; i < 2; i++) {
            int f4 = tid + 128 * i;
            int row = f4 >> 2;
            int cq  = (f4 & 3) << 2;
            int soff = (row * 16 + hswz(row, cq)) * 4;
            CP_ASYNC16(sb + soff, &B[(size_t)(bn0 + row) * DDIM + k0 + cq * 2]);
        }
        CP_COMMIT();
    };

    issue_stage(0, 0);
    issue_stage(1, 1);
    issue_stage(2, 2);

    for (int kt = 0; kt < 16; kt++) {
        if (kt < 13) issue_stage(kt + 3, (kt + 3) & 3);
        CP_WAIT(3);
        __syncthreads();

        const uint32_t* sA = smP + (kt & 3) * 3072;
        const uint32_t* sB = sA + 2048;
#pragma unroll
        for (int step = 0; step < 2; step++) {
            const int s8 = step * 8;
            uint32_t af[4][4];
#pragma unroll
            for (int mt = 0; mt < 4; mt++) {
                int r = m0 + mt * 16 + gid;
                af[mt][0] = sA[r * 16 + hswz(r, s8 + tid4)];
                af[mt][1] = sA[(r + 8) * 16 + hswz(r + 8, s8 + tid4)];
                af[mt][2] = sA[r * 16 + hswz(r, s8 + tid4 + 4)];
                af[mt][3] = sA[(r + 8) * 16 + hswz(r + 8, s8 + tid4 + 4)];
            }
            uint32_t bf[4][2];
#pragma unroll
            for (int nt = 0; nt < 4; nt++) {
                int nn = n0 + nt * 8 + gid;
                bf[nt][0] = sB[nn * 16 + hswz(nn, s8 + tid4)];
                bf[nt][1] = sB[nn * 16 + hswz(nn, s8 + tid4 + 4)];
            }
#pragma unroll
            for (int mt = 0; mt < 4; mt++)
#pragma unroll
                for (int nt = 0; nt < 4; nt++)
                    mma_f16(acc[mt][nt], af[mt], bf[nt]);
        }
        __syncthreads();
    }

    const bool act = (which < 2);
#pragma unroll
    for (int mt = 0; mt < 4; mt++) {
#pragma unroll
        for (int nt = 0; nt < 4; nt++) {
            int row = am0 + m0 + mt * 16 + gid;
            int col = bn0 + n0 + nt * 8 + tid4 * 2;
            float v0 = acc[mt][nt][0], v1 = acc[mt][nt][1];
            float v2 = acc[mt][nt][2], v3 = acc[mt][nt][3];
            if (act) {
                v0 = softplus_f(v0); v1 = softplus_f(v1);
                v2 = softplus_f(v2); v3 = softplus_f(v3);
            }
            *(float2*)&out[(size_t)row * DDIM + col] = make_float2(v0, v1);
            *(float2*)&out[(size_t)(row + 8) * DDIM + col] = make_float2(v2, v3);
        }
    }
}

// ---------------------------------------------------------------------------
// Kernel B: per-chunk KV state via warp tf32 mma. INTERLEAVED feature order
// (f = 2d -> cos, 2d+1 -> sin) to match attn_out's fp16 pair layout.
// ---------------------------------------------------------------------------
__global__ __launch_bounds__(512) void chunk_state_kernel(const float* __restrict__ pw) {
    extern __shared__ __align__(16) float smB[];
    float* sKf = smB;                // [t][f] stride SFT
    float* sV  = smB + 128*SFT;      // [t][e] stride SVE

    const int nh = blockIdx.x, c = blockIdx.y;
    const int n = nh >> 3, h = nh & 7;
    const int tid = threadIdx.x;
    const int wid = tid >> 5, lane = tid & 31;
    const int gid = lane >> 2, tid4 = lane & 3;

    for (int idx = tid; idx < 128*64; idx += 512) {
        int t = idx >> 6, di = idx & 63;
        int tg = c * TCH + t;
        int gbase = ((n << 10) + tg) * DDIM + (h << 6) + di;
        float kv = g_K[gbase];
        float vv = g_V[gbase];
        float w  = pw[(h << 6) + di];
        float s, cs;
        sincosf((float)tg * w, &s, &cs);
        sKf[t*SFT + 2*di]     = f2tf_f(kv * cs);
        sKf[t*SFT + 2*di + 1] = f2tf_f(kv * s);
        sV[t*SVE + di]        = f2tf_f(vv);
    }
    __syncthreads();

    const uint32_t* sKf32 = (const uint32_t*)sKf;
    const uint32_t* sV32  = (const uint32_t*)sV;
    const int m0 = (wid & 3) * 32;
    const int n0 = (wid >> 2) * 16;
    float acc[2][2][4] = {};
#pragma unroll
    for (int k8 = 0; k8 < 16; k8++) {
        const int kk = k8 * 8 + tid4;
        uint32_t af[2][4];
#pragma unroll
        for (int mt = 0; mt < 2; mt++) {
            int r = m0 + mt * 16 + gid;
            af[mt][0] = sKf32[kk*SFT + r];
            af[mt][1] = sKf32[kk*SFT + r + 8];
            af[mt][2] = sKf32[(kk+4)*SFT + r];
            af[mt][3] = sKf32[(kk+4)*SFT + r + 8];
        }
        uint32_t bf[2][2];
#pragma unroll
        for (int nt = 0; nt < 2; nt++) {
            int nn = n0 + nt * 8 + gid;
            bf[nt][0] = sV32[kk*SVE + nn];
            bf[nt][1] = sV32[(kk+4)*SVE + nn];
        }
#pragma unroll
        for (int mt = 0; mt < 2; mt++)
#pragma unroll
            for (int nt = 0; nt < 2; nt++)
                mma_tf32(acc[mt][nt], af[mt], bf[nt]);
    }
    size_t base = (size_t)(nh * NCH + c) * SROW;
#pragma unroll
    for (int mt = 0; mt < 2; mt++) {
#pragma unroll
        for (int nt = 0; nt < 2; nt++) {
            int f = m0 + mt * 16 + gid;
            int e = n0 + nt * 8 + tid4 * 2;
            *(float2*)&g_S[base + (size_t)f * 64 + e] =
                make_float2(acc[mt][nt][0], acc[mt][nt][1]);
            *(float2*)&g_S[base + (size_t)(f + 8) * 64 + e] =
                make_float2(acc[mt][nt][2], acc[mt][nt][3]);
        }
    }
    if (tid < 128) {
        float s = 0.0f;
        for (int t = 0; t < 128; t++) s += sKf[t*SFT + tid];
        g_S[base + 8192 + tid] = s;
    }
}

// ---------------------------------------------------------------------------
// Kernel D: per-chunk output — fp16 MMA with interleaved (cos,sin) pairs.
// smem (b32): sQTh 0 | sKTh 8704 (reused as sATh) | sVh 17408 | sPh 22016 |
//   sPden 26624 | sDen 26752 | sCB 26880 | sSB 26944  -> 27008 b32 = 108032 B
// ---------------------------------------------------------------------------
__global__ __launch_bounds__(1024, 1) void attn_out_kernel(
        const float* __restrict__ pw, const float* __restrict__ pb,
        const float* __restrict__ coeff, float* __restrict__ out) {
    extern __shared__ __align__(16) uint32_t smU[];
    uint32_t* sQTh = smU;            // [d pair][t]
    uint32_t* sKTh = smU + 8704;     // [d pair][t], reused as sATh [t' pair][row]
    uint32_t* sVh  = smU + 17408;    // [t pair][e]
    uint32_t* sPh  = smU + 22016;    // [f pair][e]
    float* sPden = (float*)(smU + 26624);
    float* sDen  = (float*)(smU + 26752);
    float* sCB   = (float*)(smU + 26880);
    float* sSB   = (float*)(smU + 26944);

    const int nh = blockIdx.x, c = blockIdx.y;
    const int n = nh >> 3, h = nh & 7;
    const int tid = threadIdx.x;
    const int wid = tid >> 5, lane = tid & 31;
    const int gid = lane >> 2, tid4 = lane & 3;

    if (tid < 128) sDen[tid] = 0.0f;
    if (tid >= 128 && tid < 192) {
        int di = tid - 128;
        float sb_, cb_;
        sincosf(pb[(h << 6) + di], &sb_, &cb_);
        sCB[di] = cb_; sSB[di] = sb_;
    }
    __syncthreads();

    // Phase 1a: features, packed (cos,sin) per half2
    for (int idx = tid; idx < 128*64; idx += 1024) {
        int t = idx >> 6, di = idx & 63;
        int tg = c * TCH + t;
        int gbase = ((n << 10) + tg) * DDIM + (h << 6) + di;
        float qv = g_Q[gbase], kv = g_K[gbase];
        float w  = pw[(h << 6) + di];
        float cf = coeff[(h << 6) + di];
        float sk, ck;
        sincosf((float)tg * w, &sk, &ck);
        float cb_ = sCB[di], sb_ = sSB[di];
        float cq = ck * cb_ - sk * sb_;
        float sq = sk * cb_ + ck * sb_;
        float qc = qv * cf;
        sQTh[di*SH + t] = pack_h2(qc * cq, qc * sq);
        sKTh[di*SH + t] = pack_h2(kv * ck, kv * sk);
    }
    // Phase 1a': V, packed pairs along t
    for (int idx = tid; idx < 64*64; idx += 1024) {
        int tp = idx >> 6, e = idx & 63;
        int gb = ((n << 10) + c * TCH + 2*tp) * DDIM + (h << 6) + e;
        float v0 = g_V[gb];
        float v1 = g_V[gb + DDIM];
        sVh[tp*SVH + e] = pack_h2(v0, v1);
    }
    // Phase 1b: inline prefix reduction, packed pairs along f (MLP batched)
    if (c > 0) {
        size_t sb = (size_t)nh * NCH * SROW;
        for (int idx = tid; idx < 64*64; idx += 1024) {
            int fp = idx >> 6, e = idx & 63;
            size_t i0 = sb + (size_t)(2*fp) * 64 + e;
            size_t i1 = i0 + 64;
            float a0 = g_S[i0], b0 = g_S[i1];
            float a1 = g_S[i0 + 1*SROW], b1 = g_S[i1 + 1*SROW];
            float a2 = g_S[i0 + 2*SROW], b2 = g_S[i1 + 2*SROW];
            float a3 = g_S[i0 + 3*SROW], b3 = g_S[i1 + 3*SROW];
            float a4 = g_S[i0 + 4*SROW], b4 = g_S[i1 + 4*SROW];
            float a5 = g_S[i0 + 5*SROW], b5 = g_S[i1 + 5*SROW];
            float a6 = g_S[i0 + 6*SROW], b6 = g_S[i1 + 6*SROW];
            float A = a0, B = b0;
            if (c > 1) { A += a1; B += b1; }
            if (c > 2) { A += a2; B += b2; }
            if (c > 3) { A += a3; B += b3; }
            if (c > 4) { A += a4; B += b4; }
            if (c > 5) { A += a5; B += b5; }
            if (c > 6) { A += a6; B += b6; }
            sPh[fp*SVH + e] = pack_h2(A, B);
        }
        if (tid < 128) {
            size_t i0 = sb + 8192 + tid;
            float v0 = g_S[i0];
            float v1 = g_S[i0 + 1*SROW];
            float v2 = g_S[i0 + 2*SROW];
            float v3 = g_S[i0 + 3*SROW];
            float v4 = g_S[i0 + 4*SROW];
            float v5 = g_S[i0 + 5*SROW];
            float v6 = g_S[i0 + 6*SROW];
            float a = v0;
            if (c > 1) a += v1;
            if (c > 2) a += v2;
            if (c > 3) a += v3;
            if (c > 4) a += v4;
            if (c > 5) a += v5;
            if (c > 6) a += v6;
            sPden[tid] = a;
        }
    }
    __syncthreads();

    // Phase 2: scores (128x128), k = 64 pairs, 8 k16 steps, warp tile 32x16
    const int m2 = (wid & 3) * 32;
    const int n2 = (wid >> 2) * 16;
    float acc[2][2][4] = {};
#pragma unroll
    for (int s = 0; s < 8; s++) {
        const int kp0 = s * 8 + tid4, kp1 = kp0 + 4;
        uint32_t af[2][4];
#pragma unroll
        for (int mt = 0; mt < 2; mt++) {
            int r = m2 + mt * 16 + gid;
            af[mt][0] = sQTh[kp0*SH + r];
            af[mt][1] = sQTh[kp0*SH + r + 8];
            af[mt][2] = sQTh[kp1*SH + r];
            af[mt][3] = sQTh[kp1*SH + r + 8];
        }
        uint32_t bf[2][2];
#pragma unroll
        for (int nt = 0; nt < 2; nt++) {
            int nn = n2 + nt * 8 + gid;
            bf[nt][0] = sKTh[kp0*SH + nn];
            bf[nt][1] = sKTh[kp1*SH + nn];
        }
#pragma unroll
        for (int mt = 0; mt < 2; mt++)
#pragma unroll
            for (int nt = 0; nt < 2; nt++)
                mma_f16(acc[mt][nt], af[mt], bf[nt]);
    }
    __syncthreads();   // all warps done reading sKTh

    // Causal mask -> packed half2 (col pairs) into sATh [t'pair][row], row sums
    uint32_t* sATh = sKTh;
#pragma unroll
    for (int mt = 0; mt < 2; mt++) {
        int r = m2 + mt * 16 + gid;
        float rs_lo = 0.0f, rs_hi = 0.0f;
#pragma unroll
        for (int nt = 0; nt < 2; nt++) {
            int cb = n2 + nt * 8 + tid4 * 2;
            int cbp = (cb >> 1);
            float v0 = (cb     <= r)     ? acc[mt][nt][0] : 0.0f;
            float v1 = (cb + 1 <= r)     ? acc[mt][nt][1] : 0.0f;
            float v2 = (cb     <= r + 8) ? acc[mt][nt][2] : 0.0f;
            float v3 = (cb + 1 <= r + 8) ? acc[mt][nt][3] : 0.0f;
            sATh[cbp*SH + r]     = pack_h2(v0, v1);
            sATh[cbp*SH + r + 8] = pack_h2(v2, v3);
            rs_lo += v0 + v1;
            rs_hi += v2 + v3;
        }
        atomicAdd(&sDen[r], rs_lo);
        atomicAdd(&sDen[r + 8], rs_hi);
    }
    __syncthreads();

    // Phase 3: out = A@V + PhiQ^T@P (128x64), 8 k16 steps each, tile 16x16
    const int m3 = (wid & 7) * 16;
    const int n3 = (wid >> 3) * 16;
    float o[2][4] = {};
#pragma unroll
    for (int s = 0; s < 8; s++) {
        const int kp0 = s * 8 + tid4, kp1 = kp0 + 4;
        uint32_t af[4];
        {
            int r = m3 + gid;
            af[0] = sATh[kp0*SH + r];
            af[1] = sATh[kp0*SH + r + 8];
            af[2] = sATh[kp1*SH + r];
            af[3] = sATh[kp1*SH + r + 8];
        }
        uint32_t bf[2][2];
#pragma unroll
        for (int nt = 0; nt < 2; nt++) {
            int nn = n3 + nt * 8 + gid;
            bf[nt][0] = sVh[kp0*SVH + nn];
            bf[nt][1] = sVh[kp1*SVH + nn];
        }
#pragma unroll
        for (int nt = 0; nt < 2; nt++)
            mma_f16(o[nt], af, bf[nt]);
    }
    if (c > 0) {
#pragma unroll
        for (int s = 0; s < 8; s++) {
            const int kp0 = s * 8 + tid4, kp1 = kp0 + 4;
            uint32_t af[4];
            {
                int r = m3 + gid;
                af[0] = sQTh[kp0*SH + r];
                af[1] = sQTh[kp0*SH + r + 8];
                af[2] = sQTh[kp1*SH + r];
                af[3] = sQTh[kp1*SH + r + 8];
            }
            uint32_t bf[2][2];
#pragma unroll
            for (int nt = 0; nt < 2; nt++) {
                int nn = n3 + nt * 8 + gid;
                bf[nt][0] = sPh[kp0*SVH + nn];
                bf[nt][1] = sPh[kp1*SVH + nn];
            }
#pragma unroll
            for (int nt = 0; nt < 2; nt++)
                mma_f16(o[nt], af, bf[nt]);
        }
        // den inter-chunk term (fp32, 8-way split over 64 f-pairs)
        int t = tid & 127, part = tid >> 7;
        float s = 0.0f;
        for (int fp = part * 8; fp < part * 8 + 8; fp++) {
            __half2 h = *(__half2*)&sQTh[fp*SH + t];
            s += __low2float(h) * sPden[2*fp] + __high2float(h) * sPden[2*fp + 1];
        }
        atomicAdd(&sDen[t], s);
    }
    __syncthreads();

    // Phase 4: normalize + write (N, Lq, H*dh)
    {
        int r = m3 + gid;
        float inv_lo = 1.0f / sDen[r];
        float inv_hi = 1.0f / sDen[r + 8];
        int tg_lo = c * TCH + r;
        int tg_hi = tg_lo + 8;
#pragma unroll
        for (int nt = 0; nt < 2; nt++) {
            int e = n3 + nt * 8 + tid4 * 2;
            *(float2*)&out[((n << 10) + tg_lo) * DDIM + (h << 6) + e] =
                make_float2(o[nt][0] * inv_lo, o[nt][1] * inv_lo);
            *(float2*)&out[((n << 10) + tg_hi) * DDIM + (h << 6) + e] =
                make_float2(o[nt][2] * inv_hi, o[nt][3] * inv_hi);
        }
    }
}

// ---------------------------------------------------------------------------
extern "C" void kernel_launch(void* const* d_in, const int* in_sizes, int n_in,
                              void* d_out, int out_size) {
    const float* query = (const float*)d_in[0];
    const float* key   = (const float*)d_in[1];
    const float* Wq    = (const float*)d_in[2];
    const float* Wk    = (const float*)d_in[3];
    const float* Wv    = (const float*)d_in[4];
    const float* coeff = (const float*)d_in[5];
    const float* pw    = (const float*)d_in[6];
    const float* pb    = (const float*)d_in[7];
    float* out = (float*)d_out;

    cudaFuncSetAttribute(proj_mma_kernel,
                         cudaFuncAttributeMaxDynamicSharedMemorySize, 49152);
    cudaFuncSetAttribute(chunk_state_kernel,
                         cudaFuncAttributeMaxDynamicSharedMemorySize, 107520);
    cudaFuncSetAttribute(attn_out_kernel,
                         cudaFuncAttributeMaxDynamicSharedMemorySize, 108032);

    conv_half_kernel<<<dim3(1024, 5), 256>>>(query, key, Wq, Wk, Wv);
    proj_mma_kernel<<<dim3(MROWS/128, DDIM/64, 3), 128, 49152>>>();
    chunk_state_kernel<<<dim3(NHH, NCH-1), 512, 107520>>>(pw);
    attn_out_kernel<<<dim3(NHH, NCH), 1024, 108032>>>(pw, pb, coeff, out);
}